// round 6
// baseline (speedup 1.0000x reference)
#include <cuda_runtime.h>
#include <math.h>

// Problem constants
#define H   1024
#define FF  4096
#define E   8
#define T   2048

// GEMM tiling: CTA 128x256x16, 8 warps of 64x64
#define BM  128
#define BN  256
#define BK  16
#define KP  20          // padded smem row stride (floats): conflict-free fragment LDS

// -------- device scratch (no allocations allowed) --------
__device__ int   g_cnt[E];
__device__ int   g_tok[E * T];           // token index per (expert, slot)
__device__ int   g_prow[E * T];          // hact row id = 2*t + k
__device__ float g_w[E * T];             // normalized routing weight
__device__ float g_hact[(size_t)2 * T * FF];   // 64 MB fp32 scratch

// -------- helpers --------
__device__ __forceinline__ unsigned f2tf(float x) {
    unsigned u;
    asm("cvt.rna.tf32.f32 %0, %1;" : "=r"(u) : "f"(x));
    return u;
}
__device__ __forceinline__ float4 cv4(float4 v) {
    float4 o;
    o.x = __uint_as_float(f2tf(v.x));
    o.y = __uint_as_float(f2tf(v.y));
    o.z = __uint_as_float(f2tf(v.z));
    o.w = __uint_as_float(f2tf(v.w));
    return o;
}
__device__ __forceinline__ float gelu_exact(float x) {
    return 0.5f * x * (1.0f + erff(x * 0.70710678118654752440f));
}
__device__ __forceinline__ void mma8(float* c, const unsigned* a, const unsigned* b) {
    asm("mma.sync.aligned.m16n8k8.row.col.f32.tf32.tf32.f32 "
        "{%0,%1,%2,%3}, {%4,%5,%6,%7}, {%8,%9}, {%0,%1,%2,%3};\n"
        : "+f"(c[0]), "+f"(c[1]), "+f"(c[2]), "+f"(c[3])
        : "r"(a[0]), "r"(a[1]), "r"(a[2]), "r"(a[3]), "r"(b[0]), "r"(b[1]));
}

// dynamic smem layout (floats): A: 2 stages x 128*KP, B: 2 stages x 256*KP
#define A_STG (BM * KP)                  // 2560
#define B_STG (BN * KP)                  // 5120
#define DSMEM_FLOATS (2 * A_STG + 2 * B_STG)   // 15360 floats = 61440 B

// ============================================================
// Kernel 0: zero output + counters
// ============================================================
__global__ void zero_kernel(float* __restrict__ out) {
    int i = blockIdx.x * blockDim.x + threadIdx.x;
    if (i < T * H) out[i] = 0.0f;
    if (i < E) g_cnt[i] = 0;
}

// ============================================================
// Kernel 1: router — one warp per token
// ============================================================
__global__ void router_kernel(const float* __restrict__ X, const float* __restrict__ GW) {
    int warp = (blockIdx.x * blockDim.x + threadIdx.x) >> 5;
    int lane = threadIdx.x & 31;
    if (warp >= T) return;
    const float* x = X + (size_t)warp * H;

    float xr[32];
#pragma unroll
    for (int i = 0; i < 32; i++) xr[i] = x[lane + 32 * i];

    float logit[E];
#pragma unroll
    for (int e = 0; e < E; e++) {
        const float* gw = GW + (size_t)e * H;
        float s = 0.0f;
#pragma unroll
        for (int i = 0; i < 32; i++) s += xr[i] * gw[lane + 32 * i];
#pragma unroll
        for (int off = 16; off > 0; off >>= 1) s += __shfl_xor_sync(0xFFFFFFFFu, s, off);
        logit[e] = s;
    }

    if (lane == 0) {
        int e0 = 0;
        float l0 = logit[0];
#pragma unroll
        for (int e = 1; e < E; e++) if (logit[e] > l0) { l0 = logit[e]; e0 = e; }
        int e1 = -1;
        float l1 = -1e30f;
#pragma unroll
        for (int e = 0; e < E; e++) if (e != e0 && logit[e] > l1) { l1 = logit[e]; e1 = e; }

        float p1 = expf(l1 - l0);
        float inv = 1.0f / (1.0f + p1);
        float w0 = inv, w1 = p1 * inv;

        int s0 = atomicAdd(&g_cnt[e0], 1);
        g_tok[e0 * T + s0]  = warp;
        g_prow[e0 * T + s0] = 2 * warp;
        g_w[e0 * T + s0]    = w0;
        int s1 = atomicAdd(&g_cnt[e1], 1);
        g_tok[e1 * T + s1]  = warp;
        g_prow[e1 * T + s1] = 2 * warp + 1;
        g_w[e1 * T + s1]    = w1;
    }
}

// ============================================================
// Shared compute macro: 64x64 warp tile, one BK=16 slab
//   A, B: smem pointers (current stage)
// ============================================================
#define COMPUTE_TILE(A, B)                                                    \
    _Pragma("unroll")                                                         \
    for (int ks = 0; ks < 2; ks++) {                                          \
        int kb = ks * 8;                                                      \
        unsigned a[4][4], b[8][2];                                            \
        _Pragma("unroll")                                                     \
        for (int mi = 0; mi < 4; mi++) {                                      \
            int mb = wm + mi * 16;                                            \
            a[mi][0] = __float_as_uint((A)[(mb + g)     * KP + kb + t4]);     \
            a[mi][1] = __float_as_uint((A)[(mb + g + 8) * KP + kb + t4]);     \
            a[mi][2] = __float_as_uint((A)[(mb + g)     * KP + kb + t4 + 4]); \
            a[mi][3] = __float_as_uint((A)[(mb + g + 8) * KP + kb + t4 + 4]); \
        }                                                                     \
        _Pragma("unroll")                                                     \
        for (int ni = 0; ni < 8; ni++) {                                      \
            int nb = wn + ni * 8 + g;                                         \
            b[ni][0] = __float_as_uint((B)[nb * KP + kb + t4]);               \
            b[ni][1] = __float_as_uint((B)[nb * KP + kb + t4 + 4]);           \
        }                                                                     \
        _Pragma("unroll")                                                     \
        for (int mi = 0; mi < 4; mi++)                                        \
            _Pragma("unroll")                                                 \
            for (int ni = 0; ni < 8; ni++)                                    \
                mma8(acc[mi][ni], a[mi], b[ni]);                              \
    }

// ============================================================
// Kernel 2: grouped GEMM1 + GELU fusion
//   B smem rows interleaved: row 2j = gate col (n0c+j), row 2j+1 = up col (n0c+j)
//   -> each thread's (c, c+1) accumulator pair = (gate, up) of one FF column
// ============================================================
__global__ __launch_bounds__(256) void gemm1_kernel(
    const float* __restrict__ X, const float* __restrict__ GUW)
{
    int e   = blockIdx.z;
    int cnt = g_cnt[e];
    int m0  = blockIdx.y * BM;
    if (m0 >= cnt) return;
    int n0c = blockIdx.x * (BN / 2);          // 128 FF columns per CTA

    extern __shared__ float dsm[];
    float* As[2] = { dsm, dsm + A_STG };
    float* Bs[2] = { dsm + 2 * A_STG, dsm + 2 * A_STG + B_STG };

    __shared__ int s_tok[BM];
    __shared__ int s_prow[BM];

    int tid = threadIdx.x;
    if (tid < BM) {
        int slot = m0 + tid;
        int v = (slot < cnt);
        s_tok[tid]  = v ? g_tok[e * T + slot]  : -1;
        s_prow[tid] = v ? g_prow[e * T + slot] : 0;
    }
    __syncthreads();

    const float* wgu = GUW + (size_t)e * (2 * FF) * H;
    int lane = tid & 31, wid = tid >> 5;
    int wm = (wid & 1) * 64, wn = (wid >> 1) * 64;
    int g = lane >> 2, t4 = lane & 3;

    float acc[4][8][4];
#pragma unroll
    for (int i = 0; i < 4; i++)
#pragma unroll
        for (int j = 0; j < 8; j++)
#pragma unroll
            for (int k = 0; k < 4; k++) acc[i][j][k] = 0.0f;

    float4 va[2], vb[4];

#define LOADG1(KT) {                                                          \
    int kof = (KT) * BK;                                                      \
    _Pragma("unroll")                                                         \
    for (int i = 0; i < 2; i++) {                                             \
        int idx = tid + i * 256;                                              \
        int row = idx >> 2, q = idx & 3;                                      \
        int tk = s_tok[row];                                                  \
        va[i] = (tk >= 0) ? *(const float4*)(X + (size_t)tk * H + kof + q * 4)\
                          : make_float4(0.f, 0.f, 0.f, 0.f);                  \
    }                                                                         \
    _Pragma("unroll")                                                         \
    for (int i = 0; i < 4; i++) {                                             \
        int idx = tid + i * 256;                                              \
        int row = idx >> 2, q = idx & 3;                                      \
        const float* src = wgu + (size_t)((row & 1) * FF + n0c + (row >> 1)) * H; \
        vb[i] = *(const float4*)(src + kof + q * 4);                          \
    }                                                                         \
}
#define STORE1(BUF) {                                                         \
    _Pragma("unroll")                                                         \
    for (int i = 0; i < 2; i++) {                                             \
        int idx = tid + i * 256;                                              \
        int row = idx >> 2, q = idx & 3;                                      \
        *(float4*)&As[BUF][row * KP + 4 * q] = cv4(va[i]);                    \
    }                                                                         \
    _Pragma("unroll")                                                         \
    for (int i = 0; i < 4; i++) {                                             \
        int idx = tid + i * 256;                                              \
        int row = idx >> 2, q = idx & 3;                                      \
        *(float4*)&Bs[BUF][row * KP + 4 * q] = cv4(vb[i]);                    \
    }                                                                         \
}

    LOADG1(0);
    STORE1(0);
    __syncthreads();

    const int nK = H / BK;   // 64
    for (int kt = 0; kt < nK; kt++) {
        int cur = kt & 1;
        if (kt + 1 < nK) LOADG1(kt + 1);
        COMPUTE_TILE(As[cur], Bs[cur]);
        if (kt + 1 < nK) STORE1(cur ^ 1);
        __syncthreads();
    }

    // epilogue: hact[prow, n0c + j] = up * gelu(gate)
#pragma unroll
    for (int mi = 0; mi < 4; mi++) {
        int row0 = wm + mi * 16 + g;
#pragma unroll
        for (int ni = 0; ni < 8; ni++) {
            int j = (wn >> 1) + ni * 4 + t4;
            if (m0 + row0 < cnt) {
                g_hact[(size_t)s_prow[row0] * FF + n0c + j] =
                    acc[mi][ni][1] * gelu_exact(acc[mi][ni][0]);
            }
            if (m0 + row0 + 8 < cnt) {
                g_hact[(size_t)s_prow[row0 + 8] * FF + n0c + j] =
                    acc[mi][ni][3] * gelu_exact(acc[mi][ni][2]);
            }
        }
    }
#undef LOADG1
#undef STORE1
}

// ============================================================
// Kernel 3: grouped GEMM2 + weighted scatter
// ============================================================
__global__ __launch_bounds__(256) void gemm2_kernel(
    const float* __restrict__ DW, float* __restrict__ out)
{
    int e   = blockIdx.z;
    int cnt = g_cnt[e];
    int m0  = blockIdx.y * BM;
    if (m0 >= cnt) return;
    int n0  = blockIdx.x * BN;

    extern __shared__ float dsm[];
    float* As[2] = { dsm, dsm + A_STG };
    float* Bs[2] = { dsm + 2 * A_STG, dsm + 2 * A_STG + B_STG };

    __shared__ int   s_prow[BM];
    __shared__ int   s_tok[BM];
    __shared__ float s_w[BM];

    int tid = threadIdx.x;
    if (tid < BM) {
        int slot = m0 + tid;
        int v = (slot < cnt);
        s_prow[tid] = v ? g_prow[e * T + slot] : -1;
        s_tok[tid]  = v ? g_tok[e * T + slot]  : 0;
        s_w[tid]    = v ? g_w[e * T + slot]    : 0.0f;
    }
    __syncthreads();

    const float* dw = DW + (size_t)e * H * FF;
    int lane = tid & 31, wid = tid >> 5;
    int wm = (wid & 1) * 64, wn = (wid >> 1) * 64;
    int g = lane >> 2, t4 = lane & 3;

    float acc[4][8][4];
#pragma unroll
    for (int i = 0; i < 4; i++)
#pragma unroll
        for (int j = 0; j < 8; j++)
#pragma unroll
            for (int k = 0; k < 4; k++) acc[i][j][k] = 0.0f;

    float4 va[2], vb[4];

#define LOADG2(KT) {                                                          \
    int kof = (KT) * BK;                                                      \
    _Pragma("unroll")                                                         \
    for (int i = 0; i < 2; i++) {                                             \
        int idx = tid + i * 256;                                              \
        int row = idx >> 2, q = idx & 3;                                      \
        int p = s_prow[row];                                                  \
        va[i] = (p >= 0) ? *(const float4*)(g_hact + (size_t)p * FF + kof + q * 4) \
                         : make_float4(0.f, 0.f, 0.f, 0.f);                   \
    }                                                                         \
    _Pragma("unroll")                                                         \
    for (int i = 0; i < 4; i++) {                                             \
        int idx = tid + i * 256;                                              \
        int row = idx >> 2, q = idx & 3;                                      \
        vb[i] = *(const float4*)(dw + (size_t)(n0 + row) * FF + kof + q * 4); \
    }                                                                         \
}
#define STORE2(BUF) {                                                         \
    _Pragma("unroll")                                                         \
    for (int i = 0; i < 2; i++) {                                             \
        int idx = tid + i * 256;                                              \
        int row = idx >> 2, q = idx & 3;                                      \
        *(float4*)&As[BUF][row * KP + 4 * q] = cv4(va[i]);                    \
    }                                                                         \
    _Pragma("unroll")                                                         \
    for (int i = 0; i < 4; i++) {                                             \
        int idx = tid + i * 256;                                              \
        int row = idx >> 2, q = idx & 3;                                      \
        *(float4*)&Bs[BUF][row * KP + 4 * q] = cv4(vb[i]);                    \
    }                                                                         \
}

    LOADG2(0);
    STORE2(0);
    __syncthreads();

    const int nK = FF / BK;   // 256
    for (int kt = 0; kt < nK; kt++) {
        int cur = kt & 1;
        if (kt + 1 < nK) LOADG2(kt + 1);
        COMPUTE_TILE(As[cur], Bs[cur]);
        if (kt + 1 < nK) STORE2(cur ^ 1);
        __syncthreads();
    }

    // epilogue: out[t, n] += w * acc (exactly 2 commutative adds per element)
#pragma unroll
    for (int mi = 0; mi < 4; mi++) {
        int row0 = wm + mi * 16 + g;
#pragma unroll
        for (int ni = 0; ni < 8; ni++) {
            int c = wn + ni * 8 + 2 * t4;
            if (m0 + row0 < cnt) {
                int   t  = s_tok[row0];
                float wt = s_w[row0];
                atomicAdd(&out[(size_t)t * H + n0 + c],     wt * acc[mi][ni][0]);
                atomicAdd(&out[(size_t)t * H + n0 + c + 1], wt * acc[mi][ni][1]);
            }
            if (m0 + row0 + 8 < cnt) {
                int   t  = s_tok[row0 + 8];
                float wt = s_w[row0 + 8];
                atomicAdd(&out[(size_t)t * H + n0 + c],     wt * acc[mi][ni][2]);
                atomicAdd(&out[(size_t)t * H + n0 + c + 1], wt * acc[mi][ni][3]);
            }
        }
    }
#undef LOADG2
#undef STORE2
}

// ============================================================
extern "C" void kernel_launch(void* const* d_in, const int* in_sizes, int n_in,
                              void* d_out, int out_size) {
    (void)in_sizes; (void)n_in; (void)out_size;
    const float* X   = (const float*)d_in[0];   // hidden_states (1,2048,1024)
    const float* GW  = (const float*)d_in[1];   // gate_w (8,1024)
    const float* GUW = (const float*)d_in[2];   // gate_up_w (8,8192,1024)
    const float* DW  = (const float*)d_in[3];   // down_w (8,1024,4096)
    float* out = (float*)d_out;                 // (1,2048,1024) fp32

    const int dsmem = DSMEM_FLOATS * (int)sizeof(float);   // 61440 B
    static int configured = 0;
    if (!configured) {
        cudaFuncSetAttribute(gemm1_kernel, cudaFuncAttributeMaxDynamicSharedMemorySize, dsmem);
        cudaFuncSetAttribute(gemm2_kernel, cudaFuncAttributeMaxDynamicSharedMemorySize, dsmem);
        configured = 1;
    }

    zero_kernel<<<(T * H + 255) / 256, 256>>>(out);
    router_kernel<<<T / 8, 256>>>(X, GW);
    gemm1_kernel<<<dim3(FF / (BN / 2), T / BM, E), 256, dsmem>>>(X, GUW);
    gemm2_kernel<<<dim3(H / BN, T / BM, E), 256, dsmem>>>(DW, out);
}

// round 8
// speedup vs baseline: 2.2151x; 2.2151x over previous
#include <cuda_runtime.h>
#include <cuda_fp16.h>
#include <math.h>

// Problem constants
#define H   1024
#define FF  4096
#define E   8
#define T   2048

// GEMM tiling: CTA 128x128x(32 halfs), 8 warps of 32x64
#define BM  128
#define BN  128
#define BK  32          // halfs per k-tile
#define AK  40          // padded smem row stride (halfs): conflict-free fragments

// -------- device scratch (no allocations allowed) --------
__device__ int    g_cnt[E];
__device__ int    g_tok[E * T];           // token index per (expert, slot)
__device__ int    g_prow[E * T];          // hact row id = 2*t + k
__device__ float  g_w[E * T];             // normalized routing weight
__device__ __half g_hact[(size_t)2 * T * FF];   // 32 MB fp16 activations

// -------- helpers --------
__device__ __forceinline__ unsigned pk(float a, float b) {
    __half2 h = __floats2half2_rn(a, b);
    return *(unsigned*)&h;
}
__device__ __forceinline__ void cvt4(unsigned* d, float4 v) {
    d[0] = pk(v.x, v.y);
    d[1] = pk(v.z, v.w);
}
__device__ __forceinline__ float gelu_exact(float x) {
    return 0.5f * x * (1.0f + erff(x * 0.70710678118654752440f));
}
__device__ __forceinline__ void mma16(float* c, const unsigned* a, const unsigned* b) {
    asm("mma.sync.aligned.m16n8k16.row.col.f32.f16.f16.f32 "
        "{%0,%1,%2,%3}, {%4,%5,%6,%7}, {%8,%9}, {%0,%1,%2,%3};\n"
        : "+f"(c[0]), "+f"(c[1]), "+f"(c[2]), "+f"(c[3])
        : "r"(a[0]), "r"(a[1]), "r"(a[2]), "r"(a[3]), "r"(b[0]), "r"(b[1]));
}

// ============================================================
// Kernel 0: zero output + counters
// ============================================================
__global__ void zero_kernel(float* __restrict__ out) {
    int i = blockIdx.x * blockDim.x + threadIdx.x;
    if (i < T * H) out[i] = 0.0f;
    if (i < E) g_cnt[i] = 0;
}

// ============================================================
// Kernel 1: router — one warp per token
// ============================================================
__global__ void router_kernel(const float* __restrict__ X, const float* __restrict__ GW) {
    int warp = (blockIdx.x * blockDim.x + threadIdx.x) >> 5;
    int lane = threadIdx.x & 31;
    if (warp >= T) return;
    const float* x = X + (size_t)warp * H;

    float xr[32];
#pragma unroll
    for (int i = 0; i < 32; i++) xr[i] = x[lane + 32 * i];

    float logit[E];
#pragma unroll
    for (int e = 0; e < E; e++) {
        const float* gw = GW + (size_t)e * H;
        float s = 0.0f;
#pragma unroll
        for (int i = 0; i < 32; i++) s += xr[i] * gw[lane + 32 * i];
#pragma unroll
        for (int off = 16; off > 0; off >>= 1) s += __shfl_xor_sync(0xFFFFFFFFu, s, off);
        logit[e] = s;
    }

    if (lane == 0) {
        int e0 = 0;
        float l0 = logit[0];
#pragma unroll
        for (int e = 1; e < E; e++) if (logit[e] > l0) { l0 = logit[e]; e0 = e; }
        int e1 = -1;
        float l1 = -1e30f;
#pragma unroll
        for (int e = 0; e < E; e++) if (e != e0 && logit[e] > l1) { l1 = logit[e]; e1 = e; }

        float p1 = expf(l1 - l0);
        float inv = 1.0f / (1.0f + p1);
        float w0 = inv, w1 = p1 * inv;

        int s0 = atomicAdd(&g_cnt[e0], 1);
        g_tok[e0 * T + s0]  = warp;
        g_prow[e0 * T + s0] = 2 * warp;
        g_w[e0 * T + s0]    = w0;
        int s1 = atomicAdd(&g_cnt[e1], 1);
        g_tok[e1 * T + s1]  = warp;
        g_prow[e1 * T + s1] = 2 * warp + 1;
        g_w[e1 * T + s1]    = w1;
    }
}

// ============================================================
// Shared compute macro: 32x64 warp tile, one BK=32 slab (2 x k16)
// ============================================================
#define COMPUTE_TILE(A, B)                                                    \
    _Pragma("unroll")                                                         \
    for (int ks = 0; ks < 2; ks++) {                                          \
        int kb = ks * 16;                                                     \
        unsigned a[2][4], b[8][2];                                            \
        _Pragma("unroll")                                                     \
        for (int mi = 0; mi < 2; mi++) {                                      \
            int mb = wm + mi * 16;                                            \
            a[mi][0] = *(const unsigned*)&(A)[(mb + g)     * AK + kb + 2*t4];     \
            a[mi][1] = *(const unsigned*)&(A)[(mb + g + 8) * AK + kb + 2*t4];     \
            a[mi][2] = *(const unsigned*)&(A)[(mb + g)     * AK + kb + 2*t4 + 8]; \
            a[mi][3] = *(const unsigned*)&(A)[(mb + g + 8) * AK + kb + 2*t4 + 8]; \
        }                                                                     \
        _Pragma("unroll")                                                     \
        for (int ni = 0; ni < 8; ni++) {                                      \
            int nb = wn + ni * 8 + g;                                         \
            b[ni][0] = *(const unsigned*)&(B)[nb * AK + kb + 2*t4];           \
            b[ni][1] = *(const unsigned*)&(B)[nb * AK + kb + 2*t4 + 8];       \
        }                                                                     \
        _Pragma("unroll")                                                     \
        for (int mi = 0; mi < 2; mi++)                                        \
            _Pragma("unroll")                                                 \
            for (int ni = 0; ni < 8; ni++)                                    \
                mma16(acc[mi][ni], a[mi], b[ni]);                             \
    }

// ============================================================
// Kernel 2: grouped GEMM1 + GELU fusion (fp16 MMA)
//   B smem rows interleaved: row 2j = gate col (n0c+j), row 2j+1 = up col
//   blockIdx.x = M-block (fastest) so concurrent CTAs share the B tile in L2
// ============================================================
__global__ __launch_bounds__(256, 2) void gemm1_kernel(
    const float* __restrict__ X, const float* __restrict__ GUW)
{
    int e   = blockIdx.z;
    int cnt = g_cnt[e];
    int m0  = blockIdx.x * BM;
    if (m0 >= cnt) return;
    int n0c = blockIdx.y * (BN / 2);          // 64 FF columns per CTA

    __shared__ __half As[2][BM * AK];
    __shared__ __half Bs[2][BN * AK];
    __shared__ int s_tok[BM];
    __shared__ int s_prow[BM];

    int tid = threadIdx.x;
    if (tid < BM) {
        int slot = m0 + tid;
        int v = (slot < cnt);
        s_tok[tid]  = v ? g_tok[e * T + slot]  : -1;
        s_prow[tid] = v ? g_prow[e * T + slot] : 0;
    }
    __syncthreads();

    const float* wgu = GUW + (size_t)e * (2 * FF) * H;
    int lane = tid & 31, wid = tid >> 5;
    int wm = (wid & 3) * 32, wn = (wid >> 2) * 64;
    int g = lane >> 2, t4 = lane & 3;

    float acc[2][8][4];
#pragma unroll
    for (int i = 0; i < 2; i++)
#pragma unroll
        for (int j = 0; j < 8; j++)
#pragma unroll
            for (int k = 0; k < 4; k++) acc[i][j][k] = 0.0f;

    unsigned pa[8], pb[8];

#define LOADG1(KT) {                                                          \
    int kof = (KT) * BK;                                                      \
    _Pragma("unroll")                                                         \
    for (int i = 0; i < 4; i++) {                                             \
        int idx = tid + i * 256;                                              \
        int row = idx >> 3, q = idx & 7;                                      \
        int tk = s_tok[row];                                                  \
        float4 v = (tk >= 0) ? *(const float4*)(X + (size_t)tk * H + kof + 4*q)\
                             : make_float4(0.f, 0.f, 0.f, 0.f);               \
        cvt4(&pa[2 * i], v);                                                  \
    }                                                                         \
    _Pragma("unroll")                                                         \
    for (int i = 0; i < 4; i++) {                                             \
        int idx = tid + i * 256;                                              \
        int row = idx >> 3, q = idx & 7;                                      \
        const float* src = wgu + (size_t)((row & 1) * FF + n0c + (row >> 1)) * H; \
        cvt4(&pb[2 * i], *(const float4*)(src + kof + 4*q));                  \
    }                                                                         \
}
#define STORE1(BUF) {                                                         \
    _Pragma("unroll")                                                         \
    for (int i = 0; i < 4; i++) {                                             \
        int idx = tid + i * 256;                                              \
        int row = idx >> 3, q = idx & 7;                                      \
        *(uint2*)&As[BUF][row * AK + 4 * q] = make_uint2(pa[2*i], pa[2*i+1]); \
    }                                                                         \
    _Pragma("unroll")                                                         \
    for (int i = 0; i < 4; i++) {                                             \
        int idx = tid + i * 256;                                              \
        int row = idx >> 3, q = idx & 7;                                      \
        *(uint2*)&Bs[BUF][row * AK + 4 * q] = make_uint2(pb[2*i], pb[2*i+1]); \
    }                                                                         \
}

    LOADG1(0);
    STORE1(0);
    __syncthreads();

    const int nK = H / BK;   // 32
    for (int kt = 0; kt < nK; kt++) {
        int cur = kt & 1;
        if (kt + 1 < nK) LOADG1(kt + 1);
        COMPUTE_TILE(As[cur], Bs[cur]);
        if (kt + 1 < nK) STORE1(cur ^ 1);
        __syncthreads();
    }

    // epilogue: hact[prow, n0c + j] = fp16(up * gelu(gate))
#pragma unroll
    for (int mi = 0; mi < 2; mi++) {
        int row0 = wm + mi * 16 + g;
#pragma unroll
        for (int ni = 0; ni < 8; ni++) {
            int j = (wn >> 1) + ni * 4 + t4;
            if (m0 + row0 < cnt) {
                g_hact[(size_t)s_prow[row0] * FF + n0c + j] =
                    __float2half_rn(acc[mi][ni][1] * gelu_exact(acc[mi][ni][0]));
            }
            if (m0 + row0 + 8 < cnt) {
                g_hact[(size_t)s_prow[row0 + 8] * FF + n0c + j] =
                    __float2half_rn(acc[mi][ni][3] * gelu_exact(acc[mi][ni][2]));
            }
        }
    }
#undef LOADG1
#undef STORE1
}

// ============================================================
// Kernel 3: grouped GEMM2 + weighted scatter (fp16 MMA, fp16 A)
// ============================================================
__global__ __launch_bounds__(256, 2) void gemm2_kernel(
    const float* __restrict__ DW, float* __restrict__ out)
{
    int e   = blockIdx.z;
    int cnt = g_cnt[e];
    int m0  = blockIdx.x * BM;
    if (m0 >= cnt) return;
    int n0  = blockIdx.y * BN;

    __shared__ __half As[2][BM * AK];
    __shared__ __half Bs[2][BN * AK];
    __shared__ int   s_prow[BM];
    __shared__ int   s_tok[BM];
    __shared__ float s_w[BM];

    int tid = threadIdx.x;
    if (tid < BM) {
        int slot = m0 + tid;
        int v = (slot < cnt);
        s_prow[tid] = v ? g_prow[e * T + slot] : -1;
        s_tok[tid]  = v ? g_tok[e * T + slot]  : 0;
        s_w[tid]    = v ? g_w[e * T + slot]    : 0.0f;
    }
    __syncthreads();

    const float* dw = DW + (size_t)e * H * FF;
    int lane = tid & 31, wid = tid >> 5;
    int wm = (wid & 3) * 32, wn = (wid >> 2) * 64;
    int g = lane >> 2, t4 = lane & 3;

    float acc[2][8][4];
#pragma unroll
    for (int i = 0; i < 2; i++)
#pragma unroll
        for (int j = 0; j < 8; j++)
#pragma unroll
            for (int k = 0; k < 4; k++) acc[i][j][k] = 0.0f;

    uint4 pa4[2];
    unsigned pb[8];

#define LOADG2(KT) {                                                          \
    int kof = (KT) * BK;                                                      \
    _Pragma("unroll")                                                         \
    for (int i = 0; i < 2; i++) {                                             \
        int idx = tid + i * 256;                                              \
        int row = idx >> 2, q = idx & 3;                                      \
        int p = s_prow[row];                                                  \
        pa4[i] = (p >= 0) ? *(const uint4*)(g_hact + (size_t)p * FF + kof + 8*q) \
                          : make_uint4(0u, 0u, 0u, 0u);                       \
    }                                                                         \
    _Pragma("unroll")                                                         \
    for (int i = 0; i < 4; i++) {                                             \
        int idx = tid + i * 256;                                              \
        int row = idx >> 3, q = idx & 7;                                      \
        cvt4(&pb[2 * i], *(const float4*)(dw + (size_t)(n0 + row) * FF + kof + 4*q)); \
    }                                                                         \
}
#define STORE2(BUF) {                                                         \
    _Pragma("unroll")                                                         \
    for (int i = 0; i < 2; i++) {                                             \
        int idx = tid + i * 256;                                              \
        int row = idx >> 2, q = idx & 3;                                      \
        *(uint4*)&As[BUF][row * AK + 8 * q] = pa4[i];                         \
    }                                                                         \
    _Pragma("unroll")                                                         \
    for (int i = 0; i < 4; i++) {                                             \
        int idx = tid + i * 256;                                              \
        int row = idx >> 3, q = idx & 7;                                      \
        *(uint2*)&Bs[BUF][row * AK + 4 * q] = make_uint2(pb[2*i], pb[2*i+1]); \
    }                                                                         \
}

    LOADG2(0);
    STORE2(0);
    __syncthreads();

    const int nK = FF / BK;   // 128
    for (int kt = 0; kt < nK; kt++) {
        int cur = kt & 1;
        if (kt + 1 < nK) LOADG2(kt + 1);
        COMPUTE_TILE(As[cur], Bs[cur]);
        if (kt + 1 < nK) STORE2(cur ^ 1);
        __syncthreads();
    }

    // epilogue: out[t, n] += w * acc (exactly 2 commutative adds per element)
#pragma unroll
    for (int mi = 0; mi < 2; mi++) {
        int row0 = wm + mi * 16 + g;
#pragma unroll
        for (int ni = 0; ni < 8; ni++) {
            int c = wn + ni * 8 + 2 * t4;
            if (m0 + row0 < cnt) {
                int   t  = s_tok[row0];
                float wt = s_w[row0];
                atomicAdd(&out[(size_t)t * H + n0 + c],     wt * acc[mi][ni][0]);
                atomicAdd(&out[(size_t)t * H + n0 + c + 1], wt * acc[mi][ni][1]);
            }
            if (m0 + row0 + 8 < cnt) {
                int   t  = s_tok[row0 + 8];
                float wt = s_w[row0 + 8];
                atomicAdd(&out[(size_t)t * H + n0 + c],     wt * acc[mi][ni][2]);
                atomicAdd(&out[(size_t)t * H + n0 + c + 1], wt * acc[mi][ni][3]);
            }
        }
    }
#undef LOADG2
#undef STORE2
}

// ============================================================
extern "C" void kernel_launch(void* const* d_in, const int* in_sizes, int n_in,
                              void* d_out, int out_size) {
    (void)in_sizes; (void)n_in; (void)out_size;
    const float* X   = (const float*)d_in[0];   // hidden_states (1,2048,1024)
    const float* GW  = (const float*)d_in[1];   // gate_w (8,1024)
    const float* GUW = (const float*)d_in[2];   // gate_up_w (8,8192,1024)
    const float* DW  = (const float*)d_in[3];   // down_w (8,1024,4096)
    float* out = (float*)d_out;                 // (1,2048,1024) fp32

    zero_kernel<<<(T * H + 255) / 256, 256>>>(out);
    router_kernel<<<T / 8, 256>>>(X, GW);
    // x = M-blocks (fastest-varying) so concurrent CTAs share B tiles in L2
    gemm1_kernel<<<dim3(T / BM, FF / (BN / 2), E), 256>>>(X, GUW);
    gemm2_kernel<<<dim3(T / BM, H / BN, E), 256>>>(DW, out);
}

// round 12
// speedup vs baseline: 2.2714x; 1.0254x over previous
#include <cuda_runtime.h>
#include <cuda_fp16.h>
#include <math.h>

// Problem constants
#define H   1024
#define FF  4096
#define E   8
#define T   2048

// GEMM tiling: CTA 128x128x(32 halfs), 8 warps of 32x64
#define BM  128
#define BN  128
#define BK  32          // halfs per k-tile
#define AK  40          // padded smem row stride (halfs): ldmatrix conflict-free

// -------- device scratch (no allocations allowed) --------
__device__ int    g_cnt[E];
__device__ int    g_tok[E * T];           // token index per (expert, slot)
__device__ int    g_prow[E * T];          // hact row id = 2*t + k
__device__ float  g_w[E * T];             // normalized routing weight
__device__ __half g_hact[(size_t)2 * T * FF];   // 32 MB fp16 activations

// -------- helpers --------
__device__ __forceinline__ unsigned pk(float a, float b) {
    __half2 h = __floats2half2_rn(a, b);
    return *(unsigned*)&h;
}
__device__ __forceinline__ void cvt4(unsigned* d, float4 v) {
    d[0] = pk(v.x, v.y);
    d[1] = pk(v.z, v.w);
}
__device__ __forceinline__ float gelu_exact(float x) {
    return 0.5f * x * (1.0f + erff(x * 0.70710678118654752440f));
}
__device__ __forceinline__ void mma16(float* c, const unsigned* a, const unsigned* b) {
    asm("mma.sync.aligned.m16n8k16.row.col.f32.f16.f16.f32 "
        "{%0,%1,%2,%3}, {%4,%5,%6,%7}, {%8,%9}, {%0,%1,%2,%3};\n"
        : "+f"(c[0]), "+f"(c[1]), "+f"(c[2]), "+f"(c[3])
        : "r"(a[0]), "r"(a[1]), "r"(a[2]), "r"(a[3]), "r"(b[0]), "r"(b[1]));
}
__device__ __forceinline__ void ldsm4(unsigned* r, unsigned addr) {
    asm volatile("ldmatrix.sync.aligned.m8n8.x4.shared.b16 {%0,%1,%2,%3}, [%4];"
                 : "=r"(r[0]), "=r"(r[1]), "=r"(r[2]), "=r"(r[3]) : "r"(addr));
}
__device__ __forceinline__ unsigned s2u(const void* p) {
    return (unsigned)__cvta_generic_to_shared(p);
}

// ============================================================
// Kernel 0: zero output + counters
// ============================================================
__global__ void zero_kernel(float* __restrict__ out) {
    int i = blockIdx.x * blockDim.x + threadIdx.x;
    if (i < T * H) out[i] = 0.0f;
    if (i < E) g_cnt[i] = 0;
}

// ============================================================
// Kernel 1: router — one warp per token
// ============================================================
__global__ void router_kernel(const float* __restrict__ X, const float* __restrict__ GW) {
    int warp = (blockIdx.x * blockDim.x + threadIdx.x) >> 5;
    int lane = threadIdx.x & 31;
    if (warp >= T) return;
    const float* x = X + (size_t)warp * H;

    float xr[32];
#pragma unroll
    for (int i = 0; i < 32; i++) xr[i] = x[lane + 32 * i];

    float logit[E];
#pragma unroll
    for (int e = 0; e < E; e++) {
        const float* gw = GW + (size_t)e * H;
        float s = 0.0f;
#pragma unroll
        for (int i = 0; i < 32; i++) s += xr[i] * gw[lane + 32 * i];
#pragma unroll
        for (int off = 16; off > 0; off >>= 1) s += __shfl_xor_sync(0xFFFFFFFFu, s, off);
        logit[e] = s;
    }

    if (lane == 0) {
        int e0 = 0;
        float l0 = logit[0];
#pragma unroll
        for (int e = 1; e < E; e++) if (logit[e] > l0) { l0 = logit[e]; e0 = e; }
        int e1 = -1;
        float l1 = -1e30f;
#pragma unroll
        for (int e = 0; e < E; e++) if (e != e0 && logit[e] > l1) { l1 = logit[e]; e1 = e; }

        float p1 = expf(l1 - l0);
        float inv = 1.0f / (1.0f + p1);
        float w0 = inv, w1 = p1 * inv;

        int s0 = atomicAdd(&g_cnt[e0], 1);
        g_tok[e0 * T + s0]  = warp;
        g_prow[e0 * T + s0] = 2 * warp;
        g_w[e0 * T + s0]    = w0;
        int s1 = atomicAdd(&g_cnt[e1], 1);
        g_tok[e1 * T + s1]  = warp;
        g_prow[e1 * T + s1] = 2 * warp + 1;
        g_w[e1 * T + s1]    = w1;
    }
}

// ============================================================
// Compute macro: 32x64 warp tile via ldmatrix, one BK=32 slab (2 x k16)
//   ABASE/BBASE: u32 shared addresses of current stage
//   aoff0/aoff1/boff0..3: precomputed per-lane ldmatrix byte offsets
// ============================================================
#define COMPUTE_TILE(ABASE, BBASE)                                            \
    _Pragma("unroll")                                                         \
    for (int ks = 0; ks < 2; ks++) {                                          \
        unsigned a0[4], a1[4], bb[4][4];                                      \
        ldsm4(a0,    (ABASE) + aoff0 + ks * 32);                              \
        ldsm4(a1,    (ABASE) + aoff1 + ks * 32);                              \
        ldsm4(bb[0], (BBASE) + boff0 + ks * 32);                              \
        ldsm4(bb[1], (BBASE) + boff1 + ks * 32);                              \
        ldsm4(bb[2], (BBASE) + boff2 + ks * 32);                              \
        ldsm4(bb[3], (BBASE) + boff3 + ks * 32);                              \
        _Pragma("unroll")                                                     \
        for (int ni = 0; ni < 8; ni++) {                                      \
            mma16(acc[0][ni], a0, &bb[ni >> 1][(ni & 1) * 2]);                \
            mma16(acc[1][ni], a1, &bb[ni >> 1][(ni & 1) * 2]);                \
        }                                                                     \
    }

// per-lane ldmatrix offset setup (bytes): A rows = m tile, B rows = n tile
#define FRAG_OFFSETS()                                                        \
    unsigned aoff0, aoff1, boff0, boff1, boff2, boff3;                        \
    {                                                                         \
        int l15 = lane & 15, lhi = (lane >> 4) << 3;                          \
        aoff0 = (unsigned)(((wm + l15) * AK + lhi) * 2);                      \
        aoff1 = (unsigned)(((wm + 16 + l15) * AK + lhi) * 2);                 \
        int l7 = lane & 7;                                                    \
        int radd = (lane & 16) ? 8 : 0;                                       \
        int kadd = (lane & 8) ? 8 : 0;                                        \
        boff0 = (unsigned)(((wn +  0 + l7 + radd) * AK + kadd) * 2);          \
        boff1 = (unsigned)(((wn + 16 + l7 + radd) * AK + kadd) * 2);          \
        boff2 = (unsigned)(((wn + 32 + l7 + radd) * AK + kadd) * 2);          \
        boff3 = (unsigned)(((wn + 48 + l7 + radd) * AK + kadd) * 2);          \
    }

// ============================================================
// Kernel 2: grouped GEMM1 + GELU fusion (fp16 MMA)
//   B smem rows interleaved: row 2j = gate col (n0c+j), row 2j+1 = up col
// ============================================================
__global__ __launch_bounds__(256, 2) void gemm1_kernel(
    const float* __restrict__ X, const float* __restrict__ GUW)
{
    int e   = blockIdx.z;
    int cnt = g_cnt[e];
    int m0  = blockIdx.x * BM;
    if (m0 >= cnt) return;
    int n0c = blockIdx.y * (BN / 2);          // 64 FF columns per CTA

    __shared__ __half As[2][BM * AK];
    __shared__ __half Bs[2][BN * AK];
    __shared__ int s_tok[BM];
    __shared__ int s_prow[BM];

    int tid = threadIdx.x;
    if (tid < BM) {
        int slot = m0 + tid;
        int v = (slot < cnt);
        s_tok[tid]  = v ? g_tok[e * T + slot]  : -1;
        s_prow[tid] = v ? g_prow[e * T + slot] : 0;
    }
    __syncthreads();

    const float* wgu = GUW + (size_t)e * (2 * FF) * H;
    int lane = tid & 31, wid = tid >> 5;
    int wm = (wid & 3) * 32, wn = (wid >> 2) * 64;
    int g = lane >> 2, t4 = lane & 3;

    unsigned abase[2] = { s2u(As[0]), s2u(As[1]) };
    unsigned bbase[2] = { s2u(Bs[0]), s2u(Bs[1]) };
    FRAG_OFFSETS();

    float acc[2][8][4];
#pragma unroll
    for (int i = 0; i < 2; i++)
#pragma unroll
        for (int j = 0; j < 8; j++)
#pragma unroll
            for (int k = 0; k < 4; k++) acc[i][j][k] = 0.0f;

    unsigned pa[8], pb[8];

#define LOADG1(KT) {                                                          \
    int kof = (KT) * BK;                                                      \
    _Pragma("unroll")                                                         \
    for (int i = 0; i < 4; i++) {                                             \
        int idx = tid + i * 256;                                              \
        int row = idx >> 3, q = idx & 7;                                      \
        int tk = s_tok[row];                                                  \
        float4 v = (tk >= 0) ? *(const float4*)(X + (size_t)tk * H + kof + 4*q)\
                             : make_float4(0.f, 0.f, 0.f, 0.f);               \
        cvt4(&pa[2 * i], v);                                                  \
    }                                                                         \
    _Pragma("unroll")                                                         \
    for (int i = 0; i < 4; i++) {                                             \
        int idx = tid + i * 256;                                              \
        int row = idx >> 3, q = idx & 7;                                      \
        const float* src = wgu + (size_t)((row & 1) * FF + n0c + (row >> 1)) * H; \
        cvt4(&pb[2 * i], *(const float4*)(src + kof + 4*q));                  \
    }                                                                         \
}
#define STORE1(BUF) {                                                         \
    _Pragma("unroll")                                                         \
    for (int i = 0; i < 4; i++) {                                             \
        int idx = tid + i * 256;                                              \
        int row = idx >> 3, q = idx & 7;                                      \
        *(uint2*)&As[BUF][row * AK + 4 * q] = make_uint2(pa[2*i], pa[2*i+1]); \
    }                                                                         \
    _Pragma("unroll")                                                         \
    for (int i = 0; i < 4; i++) {                                             \
        int idx = tid + i * 256;                                              \
        int row = idx >> 3, q = idx & 7;                                      \
        *(uint2*)&Bs[BUF][row * AK + 4 * q] = make_uint2(pb[2*i], pb[2*i+1]); \
    }                                                                         \
}

    LOADG1(0);
    STORE1(0);
    __syncthreads();

    const int nK = H / BK;   // 32
    for (int kt = 0; kt < nK; kt++) {
        int cur = kt & 1;
        if (kt + 1 < nK) LOADG1(kt + 1);
        COMPUTE_TILE(abase[cur], bbase[cur]);
        if (kt + 1 < nK) STORE1(cur ^ 1);
        __syncthreads();
    }

    // epilogue: hact[prow, n0c + j] = fp16(up * gelu(gate))
#pragma unroll
    for (int mi = 0; mi < 2; mi++) {
        int row0 = wm + mi * 16 + g;
#pragma unroll
        for (int ni = 0; ni < 8; ni++) {
            int j = (wn >> 1) + ni * 4 + t4;
            if (m0 + row0 < cnt) {
                g_hact[(size_t)s_prow[row0] * FF + n0c + j] =
                    __float2half_rn(acc[mi][ni][1] * gelu_exact(acc[mi][ni][0]));
            }
            if (m0 + row0 + 8 < cnt) {
                g_hact[(size_t)s_prow[row0 + 8] * FF + n0c + j] =
                    __float2half_rn(acc[mi][ni][3] * gelu_exact(acc[mi][ni][2]));
            }
        }
    }
#undef LOADG1
#undef STORE1
}

// ============================================================
// Kernel 3: grouped GEMM2 + weighted scatter (fp16 MMA, fp16 A)
// ============================================================
__global__ __launch_bounds__(256, 2) void gemm2_kernel(
    const float* __restrict__ DW, float* __restrict__ out)
{
    int e   = blockIdx.z;
    int cnt = g_cnt[e];
    int m0  = blockIdx.x * BM;
    if (m0 >= cnt) return;
    int n0  = blockIdx.y * BN;

    __shared__ __half As[2][BM * AK];
    __shared__ __half Bs[2][BN * AK];
    __shared__ int   s_prow[BM];
    __shared__ int   s_tok[BM];
    __shared__ float s_w[BM];

    int tid = threadIdx.x;
    if (tid < BM) {
        int slot = m0 + tid;
        int v = (slot < cnt);
        s_prow[tid] = v ? g_prow[e * T + slot] : -1;
        s_tok[tid]  = v ? g_tok[e * T + slot]  : 0;
        s_w[tid]    = v ? g_w[e * T + slot]    : 0.0f;
    }
    __syncthreads();

    const float* dw = DW + (size_t)e * H * FF;
    int lane = tid & 31, wid = tid >> 5;
    int wm = (wid & 3) * 32, wn = (wid >> 2) * 64;
    int g = lane >> 2, t4 = lane & 3;

    unsigned abase[2] = { s2u(As[0]), s2u(As[1]) };
    unsigned bbase[2] = { s2u(Bs[0]), s2u(Bs[1]) };
    FRAG_OFFSETS();

    float acc[2][8][4];
#pragma unroll
    for (int i = 0; i < 2; i++)
#pragma unroll
        for (int j = 0; j < 8; j++)
#pragma unroll
            for (int k = 0; k < 4; k++) acc[i][j][k] = 0.0f;

    uint4 pa4[2];
    unsigned pb[8];

#define LOADG2(KT) {                                                          \
    int kof = (KT) * BK;                                                      \
    _Pragma("unroll")                                                         \
    for (int i = 0; i < 2; i++) {                                             \
        int idx = tid + i * 256;                                              \
        int row = idx >> 2, q = idx & 3;                                      \
        int p = s_prow[row];                                                  \
        pa4[i] = (p >= 0) ? *(const uint4*)(g_hact + (size_t)p * FF + kof + 8*q) \
                          : make_uint4(0u, 0u, 0u, 0u);                       \
    }                                                                         \
    _Pragma("unroll")                                                         \
    for (int i = 0; i < 4; i++) {                                             \
        int idx = tid + i * 256;                                              \
        int row = idx >> 3, q = idx & 7;                                      \
        cvt4(&pb[2 * i], *(const float4*)(dw + (size_t)(n0 + row) * FF + kof + 4*q)); \
    }                                                                         \
}
#define STORE2(BUF) {                                                         \
    _Pragma("unroll")                                                         \
    for (int i = 0; i < 2; i++) {                                             \
        int idx = tid + i * 256;                                              \
        int row = idx >> 2, q = idx & 3;                                      \
        *(uint4*)&As[BUF][row * AK + 8 * q] = pa4[i];                         \
    }                                                                         \
    _Pragma("unroll")                                                         \
    for (int i = 0; i < 4; i++) {                                             \
        int idx = tid + i * 256;                                              \
        int row = idx >> 3, q = idx & 7;                                      \
        *(uint2*)&Bs[BUF][row * AK + 4 * q] = make_uint2(pb[2*i], pb[2*i+1]); \
    }                                                                         \
}

    LOADG2(0);
    STORE2(0);
    __syncthreads();

    const int nK = FF / BK;   // 128
    for (int kt = 0; kt < nK; kt++) {
        int cur = kt & 1;
        if (kt + 1 < nK) LOADG2(kt + 1);
        COMPUTE_TILE(abase[cur], bbase[cur]);
        if (kt + 1 < nK) STORE2(cur ^ 1);
        __syncthreads();
    }

    // epilogue: out[t, n] += w * acc (exactly 2 commutative adds per element)
#pragma unroll
    for (int mi = 0; mi < 2; mi++) {
        int row0 = wm + mi * 16 + g;
#pragma unroll
        for (int ni = 0; ni < 8; ni++) {
            int c = wn + ni * 8 + 2 * t4;
            if (m0 + row0 < cnt) {
                int   t  = s_tok[row0];
                float wt = s_w[row0];
                atomicAdd(&out[(size_t)t * H + n0 + c],     wt * acc[mi][ni][0]);
                atomicAdd(&out[(size_t)t * H + n0 + c + 1], wt * acc[mi][ni][1]);
            }
            if (m0 + row0 + 8 < cnt) {
                int   t  = s_tok[row0 + 8];
                float wt = s_w[row0 + 8];
                atomicAdd(&out[(size_t)t * H + n0 + c],     wt * acc[mi][ni][2]);
                atomicAdd(&out[(size_t)t * H + n0 + c + 1], wt * acc[mi][ni][3]);
            }
        }
    }
#undef LOADG2
#undef STORE2
}

// ============================================================
extern "C" void kernel_launch(void* const* d_in, const int* in_sizes, int n_in,
                              void* d_out, int out_size) {
    (void)in_sizes; (void)n_in; (void)out_size;
    const float* X   = (const float*)d_in[0];   // hidden_states (1,2048,1024)
    const float* GW  = (const float*)d_in[1];   // gate_w (8,1024)
    const float* GUW = (const float*)d_in[2];   // gate_up_w (8,8192,1024)
    const float* DW  = (const float*)d_in[3];   // down_w (8,1024,4096)
    float* out = (float*)d_out;                 // (1,2048,1024) fp32

    zero_kernel<<<(T * H + 255) / 256, 256>>>(out);
    router_kernel<<<T / 8, 256>>>(X, GW);
    // x = M-blocks (fastest-varying) so concurrent CTAs share B tiles in L2
    gemm1_kernel<<<dim3(T / BM, FF / (BN / 2), E), 256>>>(X, GUW);
    gemm2_kernel<<<dim3(T / BM, H / BN, E), 256>>>(DW, out);
}

// round 13
// speedup vs baseline: 2.7048x; 1.1908x over previous
#include <cuda_runtime.h>
#include <cuda_fp16.h>
#include <math.h>

// Problem constants
#define H   1024
#define FF  4096
#define E   8
#define T   2048

// GEMM tiling: CTA 128x128x(32 halfs), 8 warps of 32x64, 4-stage cp.async
#define BM  128
#define BN  128
#define BK  32          // halfs per k-tile
#define AK  40          // padded smem row stride (halfs): ldmatrix conflict-free
#define NSTG 4
#define STG_A (BM * AK * 2)             // 10240 B
#define STG   (STG_A + BN * AK * 2)     // 20480 B per stage
#define SMEM_BYTES (NSTG * STG)         // 81920 B

// -------- device scratch (no allocations allowed) --------
__device__ int    g_cnt[E];
__device__ int    g_tok[E * T];
__device__ int    g_prow[E * T];
__device__ float  g_w[E * T];
__device__ __half g_hact[(size_t)2 * T * FF];        // 32 MB
__device__ __half g_xh[(size_t)T * H];               // 4 MB  fp16 X
__device__ __half g_guwh[(size_t)E * 2 * FF * H];    // 128 MB fp16 gate_up (interleaved rows)
__device__ __half g_dwh[(size_t)E * H * FF];         // 64 MB fp16 down_w

// -------- helpers --------
__device__ __forceinline__ unsigned pk(float a, float b) {
    __half2 h = __floats2half2_rn(a, b);
    return *(unsigned*)&h;
}
__device__ __forceinline__ uint2 cvh4(float4 v) {
    return make_uint2(pk(v.x, v.y), pk(v.z, v.w));
}
__device__ __forceinline__ float gelu_exact(float x) {
    return 0.5f * x * (1.0f + erff(x * 0.70710678118654752440f));
}
__device__ __forceinline__ void mma16(float* c, const unsigned* a, const unsigned* b) {
    asm("mma.sync.aligned.m16n8k16.row.col.f32.f16.f16.f32 "
        "{%0,%1,%2,%3}, {%4,%5,%6,%7}, {%8,%9}, {%0,%1,%2,%3};\n"
        : "+f"(c[0]), "+f"(c[1]), "+f"(c[2]), "+f"(c[3])
        : "r"(a[0]), "r"(a[1]), "r"(a[2]), "r"(a[3]), "r"(b[0]), "r"(b[1]));
}
__device__ __forceinline__ void ldsm4(unsigned* r, unsigned addr) {
    asm volatile("ldmatrix.sync.aligned.m8n8.x4.shared.b16 {%0,%1,%2,%3}, [%4];"
                 : "=r"(r[0]), "=r"(r[1]), "=r"(r[2]), "=r"(r[3]) : "r"(addr));
}
__device__ __forceinline__ unsigned s2u(const void* p) {
    return (unsigned)__cvta_generic_to_shared(p);
}
__device__ __forceinline__ void cpa16(unsigned dst, const void* src, int szvalid) {
    asm volatile("cp.async.cg.shared.global [%0], [%1], 16, %2;"
                 :: "r"(dst), "l"(src), "r"(szvalid) : "memory");
}
#define CP_COMMIT() asm volatile("cp.async.commit_group;" ::: "memory")
#define CP_WAIT2()  asm volatile("cp.async.wait_group 2;" ::: "memory")

// ============================================================
// Kernel 0: zero output + counters
// ============================================================
__global__ void zero_kernel(float* __restrict__ out) {
    int i = blockIdx.x * blockDim.x + threadIdx.x;
    if (i < T * H) out[i] = 0.0f;
    if (i < E) g_cnt[i] = 0;
}

// ============================================================
// Convert kernels: fp32 -> fp16 (one float4 per thread)
// ============================================================
__global__ void cvtX_kernel(const float* __restrict__ X) {
    int l = blockIdx.x * blockDim.x + threadIdx.x;           // [0, T*H/4)
    if (l >= T * H / 4) return;
    *(uint2*)(g_xh + ((size_t)l << 2)) = cvh4(*(const float4*)(X + ((size_t)l << 2)));
}
__global__ void cvtDW_kernel(const float* __restrict__ DW) {
    int l = blockIdx.x * blockDim.x + threadIdx.x;           // [0, E*H*FF/4)
    if (l >= E * H * (FF / 4)) return;
    *(uint2*)(g_dwh + ((size_t)l << 2)) = cvh4(*(const float4*)(DW + ((size_t)l << 2)));
}
// GUW: interleave rows: dst row r (within expert) = 2j+s  <- src row s*FF + j
__global__ void cvtGUW_kernel(const float* __restrict__ GUW) {
    int l = blockIdx.x * blockDim.x + threadIdx.x;           // [0, E*2FF*H/4) = 16.7M
    if (l >= E * 2 * FF * (H / 4)) return;
    int k4 = l & (H / 4 - 1);          // 0..255
    int r2 = l >> 8;                   // 0..65535
    int r  = r2 & (2 * FF - 1);        // 0..8191
    int e  = r2 >> 13;
    int srcrow = e * (2 * FF) + ((r & 1) ? FF : 0) + (r >> 1);
    *(uint2*)(g_guwh + ((size_t)l << 2)) =
        cvh4(*(const float4*)(GUW + (size_t)srcrow * H + ((size_t)k4 << 2)));
}

// ============================================================
// Kernel 1: router — one warp per token
// ============================================================
__global__ void router_kernel(const float* __restrict__ X, const float* __restrict__ GW) {
    int warp = (blockIdx.x * blockDim.x + threadIdx.x) >> 5;
    int lane = threadIdx.x & 31;
    if (warp >= T) return;
    const float* x = X + (size_t)warp * H;

    float xr[32];
#pragma unroll
    for (int i = 0; i < 32; i++) xr[i] = x[lane + 32 * i];

    float logit[E];
#pragma unroll
    for (int e = 0; e < E; e++) {
        const float* gw = GW + (size_t)e * H;
        float s = 0.0f;
#pragma unroll
        for (int i = 0; i < 32; i++) s += xr[i] * gw[lane + 32 * i];
#pragma unroll
        for (int off = 16; off > 0; off >>= 1) s += __shfl_xor_sync(0xFFFFFFFFu, s, off);
        logit[e] = s;
    }

    if (lane == 0) {
        int e0 = 0;
        float l0 = logit[0];
#pragma unroll
        for (int e = 1; e < E; e++) if (logit[e] > l0) { l0 = logit[e]; e0 = e; }
        int e1 = -1;
        float l1 = -1e30f;
#pragma unroll
        for (int e = 0; e < E; e++) if (e != e0 && logit[e] > l1) { l1 = logit[e]; e1 = e; }

        float p1 = expf(l1 - l0);
        float inv = 1.0f / (1.0f + p1);

        int s0 = atomicAdd(&g_cnt[e0], 1);
        g_tok[e0 * T + s0]  = warp;
        g_prow[e0 * T + s0] = 2 * warp;
        g_w[e0 * T + s0]    = inv;
        int s1 = atomicAdd(&g_cnt[e1], 1);
        g_tok[e1 * T + s1]  = warp;
        g_prow[e1 * T + s1] = 2 * warp + 1;
        g_w[e1 * T + s1]    = p1 * inv;
    }
}

// ============================================================
// Compute macro: 32x64 warp tile via ldmatrix, one BK=32 slab (2 x k16)
// ============================================================
#define COMPUTE_TILE(ABASE, BBASE)                                            \
    _Pragma("unroll")                                                         \
    for (int ks = 0; ks < 2; ks++) {                                          \
        unsigned a0[4], a1[4], bb[4][4];                                      \
        ldsm4(a0,    (ABASE) + aoff0 + ks * 32);                              \
        ldsm4(a1,    (ABASE) + aoff1 + ks * 32);                              \
        ldsm4(bb[0], (BBASE) + boff0 + ks * 32);                              \
        ldsm4(bb[1], (BBASE) + boff1 + ks * 32);                              \
        ldsm4(bb[2], (BBASE) + boff2 + ks * 32);                              \
        ldsm4(bb[3], (BBASE) + boff3 + ks * 32);                              \
        _Pragma("unroll")                                                     \
        for (int ni = 0; ni < 8; ni++) {                                      \
            mma16(acc[0][ni], a0, &bb[ni >> 1][(ni & 1) * 2]);                \
            mma16(acc[1][ni], a1, &bb[ni >> 1][(ni & 1) * 2]);                \
        }                                                                     \
    }

#define FRAG_OFFSETS()                                                        \
    unsigned aoff0, aoff1, boff0, boff1, boff2, boff3;                        \
    {                                                                         \
        int l15 = lane & 15, lhi = (lane >> 4) << 3;                          \
        aoff0 = (unsigned)(((wm + l15) * AK + lhi) * 2);                      \
        aoff1 = (unsigned)(((wm + 16 + l15) * AK + lhi) * 2);                 \
        int l7 = lane & 7;                                                    \
        int radd = (lane & 16) ? 8 : 0;                                       \
        int kadd = (lane & 8) ? 8 : 0;                                        \
        boff0 = (unsigned)(((wn +  0 + l7 + radd) * AK + kadd) * 2);          \
        boff1 = (unsigned)(((wn + 16 + l7 + radd) * AK + kadd) * 2);          \
        boff2 = (unsigned)(((wn + 32 + l7 + radd) * AK + kadd) * 2);          \
        boff3 = (unsigned)(((wn + 48 + l7 + radd) * AK + kadd) * 2);          \
    }

// ============================================================
// Kernel 2: grouped GEMM1 + GELU fusion (fp16 MMA, cp.async 4-stage)
// ============================================================
__global__ __launch_bounds__(256, 2) void gemm1_kernel(const char* dummy)
{
    int e   = blockIdx.z;
    int cnt = g_cnt[e];
    int m0  = blockIdx.x * BM;
    if (m0 >= cnt) return;
    int n0c = blockIdx.y * (BN / 2);          // 64 FF columns per CTA

    extern __shared__ char dsm[];
    unsigned sbase = s2u(dsm);

    __shared__ int s_tok[BM];
    __shared__ int s_prow[BM];

    int tid = threadIdx.x;
    if (tid < BM) {
        int slot = m0 + tid;
        int v = (slot < cnt);
        s_tok[tid]  = v ? g_tok[e * T + slot]  : -1;
        s_prow[tid] = v ? g_prow[e * T + slot] : 0;
    }
    __syncthreads();

    const size_t gu_base = (size_t)e * (2 * FF) + 2 * n0c;   // row base in g_guwh
    int lane = tid & 31, wid = tid >> 5;
    int wm = (wid & 3) * 32, wn = (wid >> 2) * 64;
    int g = lane >> 2, t4 = lane & 3;
    FRAG_OFFSETS();

    int lrow = tid >> 2, lc = tid & 3;        // loader coords: 4 chunks/row, 2 rows/thread

    float acc[2][8][4];
#pragma unroll
    for (int i = 0; i < 2; i++)
#pragma unroll
        for (int j = 0; j < 8; j++)
#pragma unroll
            for (int k = 0; k < 4; k++) acc[i][j][k] = 0.0f;

#define LOAD_TILE1(S, KT) {                                                   \
    int kof = (KT) * BK;                                                      \
    unsigned ab = sbase + (S) * STG, bb = ab + STG_A;                         \
    _Pragma("unroll")                                                         \
    for (int i = 0; i < 2; i++) {                                             \
        int row = lrow + i * 64;                                              \
        int tk = s_tok[row];                                                  \
        const __half* sa = g_xh + (size_t)(tk < 0 ? 0 : tk) * H + kof + lc * 8; \
        cpa16(ab + row * (AK * 2) + lc * 16, sa, tk >= 0 ? 16 : 0);           \
    }                                                                         \
    _Pragma("unroll")                                                         \
    for (int i = 0; i < 2; i++) {                                             \
        int row = lrow + i * 64;                                              \
        const __half* sb = g_guwh + (gu_base + row) * H + kof + lc * 8;       \
        cpa16(bb + row * (AK * 2) + lc * 16, sb, 16);                         \
    }                                                                         \
}

    LOAD_TILE1(0, 0); CP_COMMIT();
    LOAD_TILE1(1, 1); CP_COMMIT();
    LOAD_TILE1(2, 2); CP_COMMIT();

    const int nK = H / BK;   // 32
    for (int kt = 0; kt < nK; kt++) {
        CP_WAIT2();
        __syncthreads();
        if (kt + 3 < nK) LOAD_TILE1((kt + 3) & 3, kt + 3);
        CP_COMMIT();
        unsigned ab = sbase + (kt & 3) * STG;
        COMPUTE_TILE(ab, ab + STG_A);
    }

    // epilogue: hact[prow, n0c + j] = fp16(up * gelu(gate))
#pragma unroll
    for (int mi = 0; mi < 2; mi++) {
        int row0 = wm + mi * 16 + g;
#pragma unroll
        for (int ni = 0; ni < 8; ni++) {
            int j = (wn >> 1) + ni * 4 + t4;
            if (m0 + row0 < cnt) {
                g_hact[(size_t)s_prow[row0] * FF + n0c + j] =
                    __float2half_rn(acc[mi][ni][1] * gelu_exact(acc[mi][ni][0]));
            }
            if (m0 + row0 + 8 < cnt) {
                g_hact[(size_t)s_prow[row0 + 8] * FF + n0c + j] =
                    __float2half_rn(acc[mi][ni][3] * gelu_exact(acc[mi][ni][2]));
            }
        }
    }
#undef LOAD_TILE1
}

// ============================================================
// Kernel 3: grouped GEMM2 + weighted scatter (fp16 MMA, cp.async 4-stage)
// ============================================================
__global__ __launch_bounds__(256, 2) void gemm2_kernel(float* __restrict__ out)
{
    int e   = blockIdx.z;
    int cnt = g_cnt[e];
    int m0  = blockIdx.x * BM;
    if (m0 >= cnt) return;
    int n0  = blockIdx.y * BN;

    extern __shared__ char dsm[];
    unsigned sbase = s2u(dsm);

    __shared__ int   s_prow[BM];
    __shared__ int   s_tok[BM];
    __shared__ float s_w[BM];

    int tid = threadIdx.x;
    if (tid < BM) {
        int slot = m0 + tid;
        int v = (slot < cnt);
        s_prow[tid] = v ? g_prow[e * T + slot] : -1;
        s_tok[tid]  = v ? g_tok[e * T + slot]  : 0;
        s_w[tid]    = v ? g_w[e * T + slot]    : 0.0f;
    }
    __syncthreads();

    const size_t dw_base = (size_t)e * H + n0;   // row base in g_dwh
    int lane = tid & 31, wid = tid >> 5;
    int wm = (wid & 3) * 32, wn = (wid >> 2) * 64;
    int g = lane >> 2, t4 = lane & 3;
    FRAG_OFFSETS();

    int lrow = tid >> 2, lc = tid & 3;

    float acc[2][8][4];
#pragma unroll
    for (int i = 0; i < 2; i++)
#pragma unroll
        for (int j = 0; j < 8; j++)
#pragma unroll
            for (int k = 0; k < 4; k++) acc[i][j][k] = 0.0f;

#define LOAD_TILE2(S, KT) {                                                   \
    int kof = (KT) * BK;                                                      \
    unsigned ab = sbase + (S) * STG, bb = ab + STG_A;                         \
    _Pragma("unroll")                                                         \
    for (int i = 0; i < 2; i++) {                                             \
        int row = lrow + i * 64;                                              \
        int p = s_prow[row];                                                  \
        const __half* sa = g_hact + (size_t)(p < 0 ? 0 : p) * FF + kof + lc * 8; \
        cpa16(ab + row * (AK * 2) + lc * 16, sa, p >= 0 ? 16 : 0);            \
    }                                                                         \
    _Pragma("unroll")                                                         \
    for (int i = 0; i < 2; i++) {                                             \
        int row = lrow + i * 64;                                              \
        const __half* sb = g_dwh + (dw_base + row) * FF + kof + lc * 8;       \
        cpa16(bb + row * (AK * 2) + lc * 16, sb, 16);                         \
    }                                                                         \
}

    LOAD_TILE2(0, 0); CP_COMMIT();
    LOAD_TILE2(1, 1); CP_COMMIT();
    LOAD_TILE2(2, 2); CP_COMMIT();

    const int nK = FF / BK;   // 128
    for (int kt = 0; kt < nK; kt++) {
        CP_WAIT2();
        __syncthreads();
        if (kt + 3 < nK) LOAD_TILE2((kt + 3) & 3, kt + 3);
        CP_COMMIT();
        unsigned ab = sbase + (kt & 3) * STG;
        COMPUTE_TILE(ab, ab + STG_A);
    }

    // epilogue: out[t, n] += w * acc (exactly 2 commutative adds per element)
#pragma unroll
    for (int mi = 0; mi < 2; mi++) {
        int row0 = wm + mi * 16 + g;
#pragma unroll
        for (int ni = 0; ni < 8; ni++) {
            int c = wn + ni * 8 + 2 * t4;
            if (m0 + row0 < cnt) {
                int   t  = s_tok[row0];
                float wt = s_w[row0];
                atomicAdd(&out[(size_t)t * H + n0 + c],     wt * acc[mi][ni][0]);
                atomicAdd(&out[(size_t)t * H + n0 + c + 1], wt * acc[mi][ni][1]);
            }
            if (m0 + row0 + 8 < cnt) {
                int   t  = s_tok[row0 + 8];
                float wt = s_w[row0 + 8];
                atomicAdd(&out[(size_t)t * H + n0 + c],     wt * acc[mi][ni][2]);
                atomicAdd(&out[(size_t)t * H + n0 + c + 1], wt * acc[mi][ni][3]);
            }
        }
    }
#undef LOAD_TILE2
}

// ============================================================
extern "C" void kernel_launch(void* const* d_in, const int* in_sizes, int n_in,
                              void* d_out, int out_size) {
    (void)in_sizes; (void)n_in; (void)out_size;
    const float* X   = (const float*)d_in[0];   // hidden_states (1,2048,1024)
    const float* GW  = (const float*)d_in[1];   // gate_w (8,1024)
    const float* GUW = (const float*)d_in[2];   // gate_up_w (8,8192,1024)
    const float* DW  = (const float*)d_in[3];   // down_w (8,1024,4096)
    float* out = (float*)d_out;                 // (1,2048,1024) fp32

    cudaFuncSetAttribute(gemm1_kernel, cudaFuncAttributeMaxDynamicSharedMemorySize, SMEM_BYTES);
    cudaFuncSetAttribute(gemm2_kernel, cudaFuncAttributeMaxDynamicSharedMemorySize, SMEM_BYTES);

    zero_kernel<<<(T * H + 255) / 256, 256>>>(out);
    cvtX_kernel<<<(T * H / 4 + 255) / 256, 256>>>(X);
    cvtGUW_kernel<<<(E * 2 * FF * (H / 4) + 255) / 256, 256>>>(GUW);
    cvtDW_kernel<<<(E * H * (FF / 4) + 255) / 256, 256>>>(DW);
    router_kernel<<<T / 8, 256>>>(X, GW);
    // x = M-blocks (fastest-varying) so concurrent CTAs share B tiles in L2
    gemm1_kernel<<<dim3(T / BM, FF / (BN / 2), E), 256, SMEM_BYTES>>>(nullptr);
    gemm2_kernel<<<dim3(T / BM, H / BN, E), 256, SMEM_BYTES>>>(out);
}

// round 14
// speedup vs baseline: 2.9948x; 1.1072x over previous
#include <cuda_runtime.h>
#include <cuda_fp16.h>
#include <math.h>

// Problem constants
#define H   1024
#define FF  4096
#define E   8
#define T   2048

// GEMM tiling: CTA 128x128x(64 halfs), 8 warps of 32x64, 2-stage cp.async
#define BM  128
#define BN  128
#define BK  64          // halfs per k-tile
#define AK  72          // padded smem row stride (halfs): ldmatrix conflict-free (144B)
#define STG_A (BM * AK * 2)             // 18432 B
#define STG   (STG_A + BN * AK * 2)     // 36864 B per stage
#define SMEM_BYTES (2 * STG)            // 73728 B

// -------- device scratch (no allocations allowed) --------
__device__ int    g_cnt[E];
__device__ int    g_tok[E * T];
__device__ int    g_prow[E * T];
__device__ float  g_w[E * T];
__device__ __half g_hact[(size_t)2 * T * FF];        // 32 MB
__device__ __half g_xh[(size_t)T * H];               // 4 MB  fp16 X
__device__ __half g_guwh[(size_t)E * 2 * FF * H];    // 128 MB fp16 gate_up (interleaved rows)
__device__ __half g_dwh[(size_t)E * H * FF];         // 64 MB fp16 down_w

// -------- helpers --------
__device__ __forceinline__ unsigned pk(float a, float b) {
    __half2 h = __floats2half2_rn(a, b);
    return *(unsigned*)&h;
}
__device__ __forceinline__ uint4 cvh8(float4 a, float4 b) {
    return make_uint4(pk(a.x, a.y), pk(a.z, a.w), pk(b.x, b.y), pk(b.z, b.w));
}
__device__ __forceinline__ float gelu_exact(float x) {
    return 0.5f * x * (1.0f + erff(x * 0.70710678118654752440f));
}
__device__ __forceinline__ void mma16(float* c, const unsigned* a, const unsigned* b) {
    asm("mma.sync.aligned.m16n8k16.row.col.f32.f16.f16.f32 "
        "{%0,%1,%2,%3}, {%4,%5,%6,%7}, {%8,%9}, {%0,%1,%2,%3};\n"
        : "+f"(c[0]), "+f"(c[1]), "+f"(c[2]), "+f"(c[3])
        : "r"(a[0]), "r"(a[1]), "r"(a[2]), "r"(a[3]), "r"(b[0]), "r"(b[1]));
}
__device__ __forceinline__ void ldsm4(unsigned* r, unsigned addr) {
    asm volatile("ldmatrix.sync.aligned.m8n8.x4.shared.b16 {%0,%1,%2,%3}, [%4];"
                 : "=r"(r[0]), "=r"(r[1]), "=r"(r[2]), "=r"(r[3]) : "r"(addr));
}
__device__ __forceinline__ unsigned s2u(const void* p) {
    return (unsigned)__cvta_generic_to_shared(p);
}
__device__ __forceinline__ void cpa16(unsigned dst, const void* src, int szvalid) {
    asm volatile("cp.async.cg.shared.global [%0], [%1], 16, %2;"
                 :: "r"(dst), "l"(src), "r"(szvalid) : "memory");
}
#define CP_COMMIT() asm volatile("cp.async.commit_group;" ::: "memory")
#define CP_WAIT0()  asm volatile("cp.async.wait_group 0;" ::: "memory")

// ============================================================
// Kernel 0: zero output + counters
// ============================================================
__global__ void zero_kernel(float* __restrict__ out) {
    int i = blockIdx.x * blockDim.x + threadIdx.x;
    if (i < T * H) out[i] = 0.0f;
    if (i < E) g_cnt[i] = 0;
}

// ============================================================
// Convert kernels: fp32 -> fp16, 8 elems/thread, 16B stores
// ============================================================
__global__ void cvtX_kernel(const float* __restrict__ X) {
    int l = blockIdx.x * blockDim.x + threadIdx.x;           // [0, T*H/8)
    if (l >= T * H / 8) return;
    const float* s = X + ((size_t)l << 3);
    *(uint4*)(g_xh + ((size_t)l << 3)) = cvh8(*(const float4*)s, *(const float4*)(s + 4));
}
__global__ void cvtDW_kernel(const float* __restrict__ DW) {
    int l = blockIdx.x * blockDim.x + threadIdx.x;           // [0, E*H*FF/8)
    if (l >= E * H * (FF / 8)) return;
    const float* s = DW + ((size_t)l << 3);
    *(uint4*)(g_dwh + ((size_t)l << 3)) = cvh8(*(const float4*)s, *(const float4*)(s + 4));
}
// GUW: interleave rows: dst row r (within expert) = 2j+s  <- src row s*FF + j
__global__ void cvtGUW_kernel(const float* __restrict__ GUW) {
    int l = blockIdx.x * blockDim.x + threadIdx.x;           // [0, E*2FF*H/8)
    if (l >= E * 2 * FF * (H / 8)) return;
    int k8 = l & (H / 8 - 1);          // 0..127
    int r2 = l >> 7;
    int r  = r2 & (2 * FF - 1);        // 0..8191
    int e  = r2 >> 13;
    int srcrow = e * (2 * FF) + ((r & 1) ? FF : 0) + (r >> 1);
    const float* s = GUW + (size_t)srcrow * H + ((size_t)k8 << 3);
    *(uint4*)(g_guwh + ((size_t)l << 3)) = cvh8(*(const float4*)s, *(const float4*)(s + 4));
}

// ============================================================
// Kernel 1: router — one warp per token
// ============================================================
__global__ void router_kernel(const float* __restrict__ X, const float* __restrict__ GW) {
    int warp = (blockIdx.x * blockDim.x + threadIdx.x) >> 5;
    int lane = threadIdx.x & 31;
    if (warp >= T) return;
    const float* x = X + (size_t)warp * H;

    float xr[32];
#pragma unroll
    for (int i = 0; i < 32; i++) xr[i] = x[lane + 32 * i];

    float logit[E];
#pragma unroll
    for (int e = 0; e < E; e++) {
        const float* gw = GW + (size_t)e * H;
        float s = 0.0f;
#pragma unroll
        for (int i = 0; i < 32; i++) s += xr[i] * gw[lane + 32 * i];
#pragma unroll
        for (int off = 16; off > 0; off >>= 1) s += __shfl_xor_sync(0xFFFFFFFFu, s, off);
        logit[e] = s;
    }

    if (lane == 0) {
        int e0 = 0;
        float l0 = logit[0];
#pragma unroll
        for (int e = 1; e < E; e++) if (logit[e] > l0) { l0 = logit[e]; e0 = e; }
        int e1 = -1;
        float l1 = -1e30f;
#pragma unroll
        for (int e = 0; e < E; e++) if (e != e0 && logit[e] > l1) { l1 = logit[e]; e1 = e; }

        float p1 = expf(l1 - l0);
        float inv = 1.0f / (1.0f + p1);

        int s0 = atomicAdd(&g_cnt[e0], 1);
        g_tok[e0 * T + s0]  = warp;
        g_prow[e0 * T + s0] = 2 * warp;
        g_w[e0 * T + s0]    = inv;
        int s1 = atomicAdd(&g_cnt[e1], 1);
        g_tok[e1 * T + s1]  = warp;
        g_prow[e1 * T + s1] = 2 * warp + 1;
        g_w[e1 * T + s1]    = p1 * inv;
    }
}

// ============================================================
// Compute macro: 32x64 warp tile via ldmatrix, one BK=64 slab (4 x k16)
// ============================================================
#define COMPUTE_TILE(ABASE, BBASE)                                            \
    _Pragma("unroll")                                                         \
    for (int ks = 0; ks < 4; ks++) {                                          \
        unsigned a0[4], a1[4], bb[4][4];                                      \
        ldsm4(a0,    (ABASE) + aoff0 + ks * 32);                              \
        ldsm4(a1,    (ABASE) + aoff1 + ks * 32);                              \
        ldsm4(bb[0], (BBASE) + boff0 + ks * 32);                              \
        ldsm4(bb[1], (BBASE) + boff1 + ks * 32);                              \
        ldsm4(bb[2], (BBASE) + boff2 + ks * 32);                              \
        ldsm4(bb[3], (BBASE) + boff3 + ks * 32);                              \
        _Pragma("unroll")                                                     \
        for (int ni = 0; ni < 8; ni++) {                                      \
            mma16(acc[0][ni], a0, &bb[ni >> 1][(ni & 1) * 2]);                \
            mma16(acc[1][ni], a1, &bb[ni >> 1][(ni & 1) * 2]);                \
        }                                                                     \
    }

#define FRAG_OFFSETS()                                                        \
    unsigned aoff0, aoff1, boff0, boff1, boff2, boff3;                        \
    {                                                                         \
        int l15 = lane & 15, lhi = (lane >> 4) << 3;                          \
        aoff0 = (unsigned)(((wm + l15) * AK + lhi) * 2);                      \
        aoff1 = (unsigned)(((wm + 16 + l15) * AK + lhi) * 2);                 \
        int l7 = lane & 7;                                                    \
        int radd = (lane & 16) ? 8 : 0;                                       \
        int kadd = (lane & 8) ? 8 : 0;                                       \
        boff0 = (unsigned)(((wn +  0 + l7 + radd) * AK + kadd) * 2);          \
        boff1 = (unsigned)(((wn + 16 + l7 + radd) * AK + kadd) * 2);          \
        boff2 = (unsigned)(((wn + 32 + l7 + radd) * AK + kadd) * 2);          \
        boff3 = (unsigned)(((wn + 48 + l7 + radd) * AK + kadd) * 2);          \
    }

// ============================================================
// Kernel 2: grouped GEMM1 + GELU fusion (fp16 MMA, 2-stage BK=64)
// ============================================================
__global__ __launch_bounds__(256, 2) void gemm1_kernel(const char* dummy)
{
    int e   = blockIdx.z;
    int cnt = g_cnt[e];
    int m0  = blockIdx.x * BM;
    if (m0 >= cnt) return;
    int n0c = blockIdx.y * (BN / 2);          // 64 FF columns per CTA

    extern __shared__ char dsm[];
    unsigned sbase = s2u(dsm);

    __shared__ int s_tok[BM];
    __shared__ int s_prow[BM];

    int tid = threadIdx.x;
    if (tid < BM) {
        int slot = m0 + tid;
        int v = (slot < cnt);
        s_tok[tid]  = v ? g_tok[e * T + slot]  : -1;
        s_prow[tid] = v ? g_prow[e * T + slot] : 0;
    }
    __syncthreads();

    const size_t gu_base = (size_t)e * (2 * FF) + 2 * n0c;   // row base in g_guwh
    int lane = tid & 31, wid = tid >> 5;
    int wm = (wid & 3) * 32, wn = (wid >> 2) * 64;
    int g = lane >> 2, t4 = lane & 3;
    FRAG_OFFSETS();

    int lrow = tid >> 3, lc = tid & 7;        // loader: 8 chunks/row, 32 rows/pass

    float acc[2][8][4];
#pragma unroll
    for (int i = 0; i < 2; i++)
#pragma unroll
        for (int j = 0; j < 8; j++)
#pragma unroll
            for (int k = 0; k < 4; k++) acc[i][j][k] = 0.0f;

#define LOAD_TILE1(S, KT) {                                                   \
    int kof = (KT) * BK;                                                      \
    unsigned ab = sbase + (S) * STG, bb = ab + STG_A;                         \
    _Pragma("unroll")                                                         \
    for (int i = 0; i < 4; i++) {                                             \
        int row = lrow + i * 32;                                              \
        int tk = s_tok[row];                                                  \
        const __half* sa = g_xh + (size_t)(tk < 0 ? 0 : tk) * H + kof + lc * 8; \
        cpa16(ab + row * (AK * 2) + lc * 16, sa, tk >= 0 ? 16 : 0);           \
    }                                                                         \
    _Pragma("unroll")                                                         \
    for (int i = 0; i < 4; i++) {                                             \
        int row = lrow + i * 32;                                              \
        const __half* sb = g_guwh + (gu_base + row) * H + kof + lc * 8;       \
        cpa16(bb + row * (AK * 2) + lc * 16, sb, 16);                         \
    }                                                                         \
}

    LOAD_TILE1(0, 0); CP_COMMIT();

    const int nK = H / BK;   // 16
    for (int kt = 0; kt < nK; kt++) {
        CP_WAIT0();
        __syncthreads();
        if (kt + 1 < nK) LOAD_TILE1((kt + 1) & 1, kt + 1);
        CP_COMMIT();
        unsigned ab = sbase + (kt & 1) * STG;
        COMPUTE_TILE(ab, ab + STG_A);
    }

    // epilogue: hact[prow, n0c + j] = fp16(up * gelu(gate))
#pragma unroll
    for (int mi = 0; mi < 2; mi++) {
        int row0 = wm + mi * 16 + g;
#pragma unroll
        for (int ni = 0; ni < 8; ni++) {
            int j = (wn >> 1) + ni * 4 + t4;
            if (m0 + row0 < cnt) {
                g_hact[(size_t)s_prow[row0] * FF + n0c + j] =
                    __float2half_rn(acc[mi][ni][1] * gelu_exact(acc[mi][ni][0]));
            }
            if (m0 + row0 + 8 < cnt) {
                g_hact[(size_t)s_prow[row0 + 8] * FF + n0c + j] =
                    __float2half_rn(acc[mi][ni][3] * gelu_exact(acc[mi][ni][2]));
            }
        }
    }
#undef LOAD_TILE1
}

// ============================================================
// Kernel 3: grouped GEMM2 + weighted scatter (fp16 MMA, 2-stage BK=64)
// ============================================================
__global__ __launch_bounds__(256, 2) void gemm2_kernel(float* __restrict__ out)
{
    int e   = blockIdx.z;
    int cnt = g_cnt[e];
    int m0  = blockIdx.x * BM;
    if (m0 >= cnt) return;
    int n0  = blockIdx.y * BN;

    extern __shared__ char dsm[];
    unsigned sbase = s2u(dsm);

    __shared__ int   s_prow[BM];
    __shared__ int   s_tok[BM];
    __shared__ float s_w[BM];

    int tid = threadIdx.x;
    if (tid < BM) {
        int slot = m0 + tid;
        int v = (slot < cnt);
        s_prow[tid] = v ? g_prow[e * T + slot] : -1;
        s_tok[tid]  = v ? g_tok[e * T + slot]  : 0;
        s_w[tid]    = v ? g_w[e * T + slot]    : 0.0f;
    }
    __syncthreads();

    const size_t dw_base = (size_t)e * H + n0;   // row base in g_dwh
    int lane = tid & 31, wid = tid >> 5;
    int wm = (wid & 3) * 32, wn = (wid >> 2) * 64;
    int g = lane >> 2, t4 = lane & 3;
    FRAG_OFFSETS();

    int lrow = tid >> 3, lc = tid & 7;

    float acc[2][8][4];
#pragma unroll
    for (int i = 0; i < 2; i++)
#pragma unroll
        for (int j = 0; j < 8; j++)
#pragma unroll
            for (int k = 0; k < 4; k++) acc[i][j][k] = 0.0f;

#define LOAD_TILE2(S, KT) {                                                   \
    int kof = (KT) * BK;                                                      \
    unsigned ab = sbase + (S) * STG, bb = ab + STG_A;                         \
    _Pragma("unroll")                                                         \
    for (int i = 0; i < 4; i++) {                                             \
        int row = lrow + i * 32;                                              \
        int p = s_prow[row];                                                  \
        const __half* sa = g_hact + (size_t)(p < 0 ? 0 : p) * FF + kof + lc * 8; \
        cpa16(ab + row * (AK * 2) + lc * 16, sa, p >= 0 ? 16 : 0);            \
    }                                                                         \
    _Pragma("unroll")                                                         \
    for (int i = 0; i < 4; i++) {                                             \
        int row = lrow + i * 32;                                              \
        const __half* sb = g_dwh + (dw_base + row) * FF + kof + lc * 8;       \
        cpa16(bb + row * (AK * 2) + lc * 16, sb, 16);                         \
    }                                                                         \
}

    LOAD_TILE2(0, 0); CP_COMMIT();

    const int nK = FF / BK;   // 64
    for (int kt = 0; kt < nK; kt++) {
        CP_WAIT0();
        __syncthreads();
        if (kt + 1 < nK) LOAD_TILE2((kt + 1) & 1, kt + 1);
        CP_COMMIT();
        unsigned ab = sbase + (kt & 1) * STG;
        COMPUTE_TILE(ab, ab + STG_A);
    }

    // epilogue: out[t, n] += w * acc (exactly 2 commutative adds per element)
#pragma unroll
    for (int mi = 0; mi < 2; mi++) {
        int row0 = wm + mi * 16 + g;
#pragma unroll
        for (int ni = 0; ni < 8; ni++) {
            int c = wn + ni * 8 + 2 * t4;
            if (m0 + row0 < cnt) {
                int   t  = s_tok[row0];
                float wt = s_w[row0];
                atomicAdd(&out[(size_t)t * H + n0 + c],     wt * acc[mi][ni][0]);
                atomicAdd(&out[(size_t)t * H + n0 + c + 1], wt * acc[mi][ni][1]);
            }
            if (m0 + row0 + 8 < cnt) {
                int   t  = s_tok[row0 + 8];
                float wt = s_w[row0 + 8];
                atomicAdd(&out[(size_t)t * H + n0 + c],     wt * acc[mi][ni][2]);
                atomicAdd(&out[(size_t)t * H + n0 + c + 1], wt * acc[mi][ni][3]);
            }
        }
    }
#undef LOAD_TILE2
}

// ============================================================
extern "C" void kernel_launch(void* const* d_in, const int* in_sizes, int n_in,
                              void* d_out, int out_size) {
    (void)in_sizes; (void)n_in; (void)out_size;
    const float* X   = (const float*)d_in[0];   // hidden_states (1,2048,1024)
    const float* GW  = (const float*)d_in[1];   // gate_w (8,1024)
    const float* GUW = (const float*)d_in[2];   // gate_up_w (8,8192,1024)
    const float* DW  = (const float*)d_in[3];   // down_w (8,1024,4096)
    float* out = (float*)d_out;                 // (1,2048,1024) fp32

    cudaFuncSetAttribute(gemm1_kernel, cudaFuncAttributeMaxDynamicSharedMemorySize, SMEM_BYTES);
    cudaFuncSetAttribute(gemm2_kernel, cudaFuncAttributeMaxDynamicSharedMemorySize, SMEM_BYTES);

    zero_kernel<<<(T * H + 255) / 256, 256>>>(out);
    cvtX_kernel<<<(T * H / 8 + 255) / 256, 256>>>(X);
    cvtGUW_kernel<<<(E * 2 * FF * (H / 8) + 255) / 256, 256>>>(GUW);
    cvtDW_kernel<<<(E * H * (FF / 8) + 255) / 256, 256>>>(DW);
    router_kernel<<<T / 8, 256>>>(X, GW);
    // x = M-blocks (fastest-varying) so concurrent CTAs share B tiles in L2
    gemm1_kernel<<<dim3(T / BM, FF / (BN / 2), E), 256, SMEM_BYTES>>>(nullptr);
    gemm2_kernel<<<dim3(T / BM, H / BN, E), 256, SMEM_BYTES>>>(out);
}

// round 15
// speedup vs baseline: 3.0568x; 1.0207x over previous
#include <cuda_runtime.h>
#include <cuda_fp16.h>
#include <math.h>

// Problem constants
#define H   1024
#define FF  4096
#define E   8
#define T   2048

// GEMM tiling: CTA 128x128x(64 halfs), 8 warps of 32x64, 2-stage cp.async
#define BM  128
#define BN  128
#define BK  64          // halfs per k-tile
#define AK  72          // padded smem row stride (halfs): ldmatrix conflict-free (144B)
#define STG_A (BM * AK * 2)             // 18432 B
#define STG   (STG_A + BN * AK * 2)     // 36864 B per stage
#define SMEM_BYTES (2 * STG)            // 73728 B

// -------- device scratch (no allocations allowed) --------
__device__ int    g_cnt[E];
__device__ int    g_tok[E * T];
__device__ int    g_prow[E * T];
__device__ float  g_w[E * T];
__device__ __half g_hact[(size_t)2 * T * FF];        // 32 MB
__device__ __half g_xh[(size_t)T * H];               // 4 MB  fp16 X
__device__ __half g_guwh[(size_t)E * 2 * FF * H];    // 128 MB fp16 gate_up (interleaved rows)
__device__ __half g_dwh[(size_t)E * H * FF];         // 64 MB fp16 down_w

// -------- helpers --------
__device__ __forceinline__ unsigned pk(float a, float b) {
    __half2 h = __floats2half2_rn(a, b);
    return *(unsigned*)&h;
}
__device__ __forceinline__ uint4 cvh8(float4 a, float4 b) {
    return make_uint4(pk(a.x, a.y), pk(a.z, a.w), pk(b.x, b.y), pk(b.z, b.w));
}
__device__ __forceinline__ float gelu_exact(float x) {
    return 0.5f * x * (1.0f + erff(x * 0.70710678118654752440f));
}
__device__ __forceinline__ void mma16(float* c, const unsigned* a, const unsigned* b) {
    asm("mma.sync.aligned.m16n8k16.row.col.f32.f16.f16.f32 "
        "{%0,%1,%2,%3}, {%4,%5,%6,%7}, {%8,%9}, {%0,%1,%2,%3};\n"
        : "+f"(c[0]), "+f"(c[1]), "+f"(c[2]), "+f"(c[3])
        : "r"(a[0]), "r"(a[1]), "r"(a[2]), "r"(a[3]), "r"(b[0]), "r"(b[1]));
}
__device__ __forceinline__ void ldsm4(unsigned* r, unsigned addr) {
    asm volatile("ldmatrix.sync.aligned.m8n8.x4.shared.b16 {%0,%1,%2,%3}, [%4];"
                 : "=r"(r[0]), "=r"(r[1]), "=r"(r[2]), "=r"(r[3]) : "r"(addr));
}
__device__ __forceinline__ unsigned s2u(const void* p) {
    return (unsigned)__cvta_generic_to_shared(p);
}
__device__ __forceinline__ void cpa16(unsigned dst, const void* src, int szvalid) {
    asm volatile("cp.async.cg.shared.global [%0], [%1], 16, %2;"
                 :: "r"(dst), "l"(src), "r"(szvalid) : "memory");
}
#define CP_COMMIT() asm volatile("cp.async.commit_group;" ::: "memory")
#define CP_WAIT0()  asm volatile("cp.async.wait_group 0;" ::: "memory")

// ============================================================
// Kernel 0: zero output + counters + convert X -> fp16 (merged)
//   grid covers T*H/8 threads; each zeroes 8 out floats + converts 8 X floats
// ============================================================
__global__ void zero_cvtX_kernel(float* __restrict__ out, const float* __restrict__ X) {
    int l = blockIdx.x * blockDim.x + threadIdx.x;           // [0, T*H/8)
    if (l < E) g_cnt[l] = 0;
    if (l >= T * H / 8) return;
    size_t off = (size_t)l << 3;
    const float* s = X + off;
    *(uint4*)(g_xh + off) = cvh8(*(const float4*)s, *(const float4*)(s + 4));
    float4 z = make_float4(0.f, 0.f, 0.f, 0.f);
    *(float4*)(out + off)     = z;
    *(float4*)(out + off + 4) = z;
}

// ============================================================
// Convert GUW: interleave rows: dst row r (within expert) = 2j+s <- src row s*FF + j
// ============================================================
__global__ void cvtGUW_kernel(const float* __restrict__ GUW) {
    int l = blockIdx.x * blockDim.x + threadIdx.x;           // [0, E*2FF*H/8)
    if (l >= E * 2 * FF * (H / 8)) return;
    int k8 = l & (H / 8 - 1);          // 0..127
    int r2 = l >> 7;
    int r  = r2 & (2 * FF - 1);        // 0..8191
    int e  = r2 >> 13;
    int srcrow = e * (2 * FF) + ((r & 1) ? FF : 0) + (r >> 1);
    const float* s = GUW + (size_t)srcrow * H + ((size_t)k8 << 3);
    *(uint4*)(g_guwh + ((size_t)l << 3)) = cvh8(*(const float4*)s, *(const float4*)(s + 4));
}

// ============================================================
// Kernel 1: router — one warp per token
// ============================================================
__global__ void router_kernel(const float* __restrict__ X, const float* __restrict__ GW) {
    int warp = (blockIdx.x * blockDim.x + threadIdx.x) >> 5;
    int lane = threadIdx.x & 31;
    if (warp >= T) return;
    const float* x = X + (size_t)warp * H;

    float xr[32];
#pragma unroll
    for (int i = 0; i < 32; i++) xr[i] = x[lane + 32 * i];

    float logit[E];
#pragma unroll
    for (int e = 0; e < E; e++) {
        const float* gw = GW + (size_t)e * H;
        float s = 0.0f;
#pragma unroll
        for (int i = 0; i < 32; i++) s += xr[i] * gw[lane + 32 * i];
#pragma unroll
        for (int off = 16; off > 0; off >>= 1) s += __shfl_xor_sync(0xFFFFFFFFu, s, off);
        logit[e] = s;
    }

    if (lane == 0) {
        int e0 = 0;
        float l0 = logit[0];
#pragma unroll
        for (int e = 1; e < E; e++) if (logit[e] > l0) { l0 = logit[e]; e0 = e; }
        int e1 = -1;
        float l1 = -1e30f;
#pragma unroll
        for (int e = 0; e < E; e++) if (e != e0 && logit[e] > l1) { l1 = logit[e]; e1 = e; }

        float p1 = expf(l1 - l0);
        float inv = 1.0f / (1.0f + p1);

        int s0 = atomicAdd(&g_cnt[e0], 1);
        g_tok[e0 * T + s0]  = warp;
        g_prow[e0 * T + s0] = 2 * warp;
        g_w[e0 * T + s0]    = inv;
        int s1 = atomicAdd(&g_cnt[e1], 1);
        g_tok[e1 * T + s1]  = warp;
        g_prow[e1 * T + s1] = 2 * warp + 1;
        g_w[e1 * T + s1]    = p1 * inv;
    }
}

// ============================================================
// Compute macro: 32x64 warp tile via ldmatrix, one BK=64 slab (4 x k16)
// ============================================================
#define COMPUTE_TILE(ABASE, BBASE)                                            \
    _Pragma("unroll")                                                         \
    for (int ks = 0; ks < 4; ks++) {                                          \
        unsigned a0[4], a1[4], bb[4][4];                                      \
        ldsm4(a0,    (ABASE) + aoff0 + ks * 32);                              \
        ldsm4(a1,    (ABASE) + aoff1 + ks * 32);                              \
        ldsm4(bb[0], (BBASE) + boff0 + ks * 32);                              \
        ldsm4(bb[1], (BBASE) + boff1 + ks * 32);                              \
        ldsm4(bb[2], (BBASE) + boff2 + ks * 32);                              \
        ldsm4(bb[3], (BBASE) + boff3 + ks * 32);                              \
        _Pragma("unroll")                                                     \
        for (int ni = 0; ni < 8; ni++) {                                      \
            mma16(acc[0][ni], a0, &bb[ni >> 1][(ni & 1) * 2]);                \
            mma16(acc[1][ni], a1, &bb[ni >> 1][(ni & 1) * 2]);                \
        }                                                                     \
    }

#define FRAG_OFFSETS()                                                        \
    unsigned aoff0, aoff1, boff0, boff1, boff2, boff3;                        \
    {                                                                         \
        int l15 = lane & 15, lhi = (lane >> 4) << 3;                          \
        aoff0 = (unsigned)(((wm + l15) * AK + lhi) * 2);                      \
        aoff1 = (unsigned)(((wm + 16 + l15) * AK + lhi) * 2);                 \
        int l7 = lane & 7;                                                    \
        int radd = (lane & 16) ? 8 : 0;                                       \
        int kadd = (lane & 8) ? 8 : 0;                                        \
        boff0 = (unsigned)(((wn +  0 + l7 + radd) * AK + kadd) * 2);          \
        boff1 = (unsigned)(((wn + 16 + l7 + radd) * AK + kadd) * 2);          \
        boff2 = (unsigned)(((wn + 32 + l7 + radd) * AK + kadd) * 2);          \
        boff3 = (unsigned)(((wn + 48 + l7 + radd) * AK + kadd) * 2);          \
    }

// ============================================================
// Kernel 2: grouped GEMM1 + GELU fusion (fp16 MMA, 2-stage BK=64)
//   + distributed DW fp32->fp16 convert (every CTA converts a 4096-float slice,
//     overlapping the DRAM-bound convert with tensor-bound GEMM work)
// ============================================================
__global__ __launch_bounds__(256, 2) void gemm1_kernel(const float* __restrict__ DW)
{
    int tid = threadIdx.x;

    // ---- distributed DW convert: disjoint slices cover E*H*FF exactly ----
    {
        unsigned b = blockIdx.x + 16u * (blockIdx.y + 64u * blockIdx.z);  // 0..8191
        size_t off = ((size_t)b << 12) + ((size_t)tid << 3);              // b*4096 + tid*8
#pragma unroll
        for (int i = 0; i < 2; i++) {
            const float* s = DW + off + i * 2048;
            *(uint4*)(g_dwh + off + i * 2048) = cvh8(*(const float4*)s, *(const float4*)(s + 4));
        }
    }

    int e   = blockIdx.z;
    int cnt = g_cnt[e];
    int m0  = blockIdx.x * BM;
    if (m0 >= cnt) return;
    int n0c = blockIdx.y * (BN / 2);          // 64 FF columns per CTA

    extern __shared__ char dsm[];
    unsigned sbase = s2u(dsm);

    __shared__ int s_tok[BM];
    __shared__ int s_prow[BM];

    if (tid < BM) {
        int slot = m0 + tid;
        int v = (slot < cnt);
        s_tok[tid]  = v ? g_tok[e * T + slot]  : -1;
        s_prow[tid] = v ? g_prow[e * T + slot] : 0;
    }
    __syncthreads();

    const size_t gu_base = (size_t)e * (2 * FF) + 2 * n0c;   // row base in g_guwh
    int lane = tid & 31, wid = tid >> 5;
    int wm = (wid & 3) * 32, wn = (wid >> 2) * 64;
    int g = lane >> 2, t4 = lane & 3;
    FRAG_OFFSETS();

    int lrow = tid >> 3, lc = tid & 7;        // loader: 8 chunks/row, 32 rows/pass

    float acc[2][8][4];
#pragma unroll
    for (int i = 0; i < 2; i++)
#pragma unroll
        for (int j = 0; j < 8; j++)
#pragma unroll
            for (int k = 0; k < 4; k++) acc[i][j][k] = 0.0f;

#define LOAD_TILE1(S, KT) {                                                   \
    int kof = (KT) * BK;                                                      \
    unsigned ab = sbase + (S) * STG, bb = ab + STG_A;                         \
    _Pragma("unroll")                                                         \
    for (int i = 0; i < 4; i++) {                                             \
        int row = lrow + i * 32;                                              \
        int tk = s_tok[row];                                                  \
        const __half* sa = g_xh + (size_t)(tk < 0 ? 0 : tk) * H + kof + lc * 8; \
        cpa16(ab + row * (AK * 2) + lc * 16, sa, tk >= 0 ? 16 : 0);           \
    }                                                                         \
    _Pragma("unroll")                                                         \
    for (int i = 0; i < 4; i++) {                                             \
        int row = lrow + i * 32;                                              \
        const __half* sb = g_guwh + (gu_base + row) * H + kof + lc * 8;       \
        cpa16(bb + row * (AK * 2) + lc * 16, sb, 16);                         \
    }                                                                         \
}

    LOAD_TILE1(0, 0); CP_COMMIT();

    const int nK = H / BK;   // 16
    for (int kt = 0; kt < nK; kt++) {
        CP_WAIT0();
        __syncthreads();
        if (kt + 1 < nK) LOAD_TILE1((kt + 1) & 1, kt + 1);
        CP_COMMIT();
        unsigned ab = sbase + (kt & 1) * STG;
        COMPUTE_TILE(ab, ab + STG_A);
    }

    // epilogue: hact[prow, n0c + j] = fp16(up * gelu(gate))
#pragma unroll
    for (int mi = 0; mi < 2; mi++) {
        int row0 = wm + mi * 16 + g;
#pragma unroll
        for (int ni = 0; ni < 8; ni++) {
            int j = (wn >> 1) + ni * 4 + t4;
            if (m0 + row0 < cnt) {
                g_hact[(size_t)s_prow[row0] * FF + n0c + j] =
                    __float2half_rn(acc[mi][ni][1] * gelu_exact(acc[mi][ni][0]));
            }
            if (m0 + row0 + 8 < cnt) {
                g_hact[(size_t)s_prow[row0 + 8] * FF + n0c + j] =
                    __float2half_rn(acc[mi][ni][3] * gelu_exact(acc[mi][ni][2]));
            }
        }
    }
#undef LOAD_TILE1
}

// ============================================================
// Kernel 3: grouped GEMM2 + weighted scatter (fp16 MMA, 2-stage BK=64)
// ============================================================
__global__ __launch_bounds__(256, 2) void gemm2_kernel(float* __restrict__ out)
{
    int e   = blockIdx.z;
    int cnt = g_cnt[e];
    int m0  = blockIdx.x * BM;
    if (m0 >= cnt) return;
    int n0  = blockIdx.y * BN;

    extern __shared__ char dsm[];
    unsigned sbase = s2u(dsm);

    __shared__ int   s_prow[BM];
    __shared__ int   s_tok[BM];
    __shared__ float s_w[BM];

    int tid = threadIdx.x;
    if (tid < BM) {
        int slot = m0 + tid;
        int v = (slot < cnt);
        s_prow[tid] = v ? g_prow[e * T + slot] : -1;
        s_tok[tid]  = v ? g_tok[e * T + slot]  : 0;
        s_w[tid]    = v ? g_w[e * T + slot]    : 0.0f;
    }
    __syncthreads();

    const size_t dw_base = (size_t)e * H + n0;   // row base in g_dwh
    int lane = tid & 31, wid = tid >> 5;
    int wm = (wid & 3) * 32, wn = (wid >> 2) * 64;
    int g = lane >> 2, t4 = lane & 3;
    FRAG_OFFSETS();

    int lrow = tid >> 3, lc = tid & 7;

    float acc[2][8][4];
#pragma unroll
    for (int i = 0; i < 2; i++)
#pragma unroll
        for (int j = 0; j < 8; j++)
#pragma unroll
            for (int k = 0; k < 4; k++) acc[i][j][k] = 0.0f;

#define LOAD_TILE2(S, KT) {                                                   \
    int kof = (KT) * BK;                                                      \
    unsigned ab = sbase + (S) * STG, bb = ab + STG_A;                         \
    _Pragma("unroll")                                                         \
    for (int i = 0; i < 4; i++) {                                             \
        int row = lrow + i * 32;                                              \
        int p = s_prow[row];                                                  \
        const __half* sa = g_hact + (size_t)(p < 0 ? 0 : p) * FF + kof + lc * 8; \
        cpa16(ab + row * (AK * 2) + lc * 16, sa, p >= 0 ? 16 : 0);            \
    }                                                                         \
    _Pragma("unroll")                                                         \
    for (int i = 0; i < 4; i++) {                                             \
        int row = lrow + i * 32;                                              \
        const __half* sb = g_dwh + (dw_base + row) * FF + kof + lc * 8;       \
        cpa16(bb + row * (AK * 2) + lc * 16, sb, 16);                         \
    }                                                                         \
}

    LOAD_TILE2(0, 0); CP_COMMIT();

    const int nK = FF / BK;   // 64
    for (int kt = 0; kt < nK; kt++) {
        CP_WAIT0();
        __syncthreads();
        if (kt + 1 < nK) LOAD_TILE2((kt + 1) & 1, kt + 1);
        CP_COMMIT();
        unsigned ab = sbase + (kt & 1) * STG;
        COMPUTE_TILE(ab, ab + STG_A);
    }

    // epilogue: out[t, n] += w * acc (exactly 2 commutative adds per element)
#pragma unroll
    for (int mi = 0; mi < 2; mi++) {
        int row0 = wm + mi * 16 + g;
#pragma unroll
        for (int ni = 0; ni < 8; ni++) {
            int c = wn + ni * 8 + 2 * t4;
            if (m0 + row0 < cnt) {
                int   t  = s_tok[row0];
                float wt = s_w[row0];
                atomicAdd(&out[(size_t)t * H + n0 + c],     wt * acc[mi][ni][0]);
                atomicAdd(&out[(size_t)t * H + n0 + c + 1], wt * acc[mi][ni][1]);
            }
            if (m0 + row0 + 8 < cnt) {
                int   t  = s_tok[row0 + 8];
                float wt = s_w[row0 + 8];
                atomicAdd(&out[(size_t)t * H + n0 + c],     wt * acc[mi][ni][2]);
                atomicAdd(&out[(size_t)t * H + n0 + c + 1], wt * acc[mi][ni][3]);
            }
        }
    }
#undef LOAD_TILE2
}

// ============================================================
extern "C" void kernel_launch(void* const* d_in, const int* in_sizes, int n_in,
                              void* d_out, int out_size) {
    (void)in_sizes; (void)n_in; (void)out_size;
    const float* X   = (const float*)d_in[0];   // hidden_states (1,2048,1024)
    const float* GW  = (const float*)d_in[1];   // gate_w (8,1024)
    const float* GUW = (const float*)d_in[2];   // gate_up_w (8,8192,1024)
    const float* DW  = (const float*)d_in[3];   // down_w (8,1024,4096)
    float* out = (float*)d_out;                 // (1,2048,1024) fp32

    cudaFuncSetAttribute(gemm1_kernel, cudaFuncAttributeMaxDynamicSharedMemorySize, SMEM_BYTES);
    cudaFuncSetAttribute(gemm2_kernel, cudaFuncAttributeMaxDynamicSharedMemorySize, SMEM_BYTES);

    zero_cvtX_kernel<<<(T * H / 8 + 255) / 256, 256>>>(out, X);
    cvtGUW_kernel<<<(E * 2 * FF * (H / 8) + 255) / 256, 256>>>(GUW);
    router_kernel<<<T / 8, 256>>>(X, GW);
    // x = M-blocks (fastest-varying) so concurrent CTAs share B tiles in L2
    gemm1_kernel<<<dim3(T / BM, FF / (BN / 2), E), 256, SMEM_BYTES>>>(DW);
    gemm2_kernel<<<dim3(T / BM, H / BN, E), 256, SMEM_BYTES>>>(out);
}

// round 16
// speedup vs baseline: 3.0708x; 1.0046x over previous
#include <cuda_runtime.h>
#include <cuda_fp16.h>
#include <math.h>

// Problem constants
#define H   1024
#define FF  4096
#define E   8
#define T   2048

// GEMM tiling: CTA 128x128x(64 halfs), 8 warps of 32x64, 3-stage cp.async
#define BM  128
#define BN  128
#define BK  64          // halfs per k-tile
#define AK  72          // padded smem row stride (halfs): ldmatrix conflict-free (144B)
#define STG_A (BM * AK * 2)             // 18432 B
#define STG   (STG_A + BN * AK * 2)     // 36864 B per stage
#define SMEM_BYTES (3 * STG)            // 110592 B

// -------- device scratch (no allocations allowed) --------
__device__ int    g_cnt[E];
__device__ int    g_tok[E * T];
__device__ int    g_prow[E * T];
__device__ float  g_w[E * T];
__device__ __half g_hact[(size_t)2 * T * FF];        // 32 MB
__device__ __half g_xh[(size_t)T * H];               // 4 MB  fp16 X
__device__ __half g_guwh[(size_t)E * 2 * FF * H];    // 128 MB fp16 gate_up (interleaved rows)
__device__ __half g_dwh[(size_t)E * H * FF];         // 64 MB fp16 down_w

// -------- helpers --------
__device__ __forceinline__ unsigned pk(float a, float b) {
    __half2 h = __floats2half2_rn(a, b);
    return *(unsigned*)&h;
}
__device__ __forceinline__ uint4 cvh8(float4 a, float4 b) {
    return make_uint4(pk(a.x, a.y), pk(a.z, a.w), pk(b.x, b.y), pk(b.z, b.w));
}
__device__ __forceinline__ float gelu_exact(float x) {
    return 0.5f * x * (1.0f + erff(x * 0.70710678118654752440f));
}
__device__ __forceinline__ void mma16(float* c, const unsigned* a, const unsigned* b) {
    asm("mma.sync.aligned.m16n8k16.row.col.f32.f16.f16.f32 "
        "{%0,%1,%2,%3}, {%4,%5,%6,%7}, {%8,%9}, {%0,%1,%2,%3};\n"
        : "+f"(c[0]), "+f"(c[1]), "+f"(c[2]), "+f"(c[3])
        : "r"(a[0]), "r"(a[1]), "r"(a[2]), "r"(a[3]), "r"(b[0]), "r"(b[1]));
}
__device__ __forceinline__ void ldsm4(unsigned* r, unsigned addr) {
    asm volatile("ldmatrix.sync.aligned.m8n8.x4.shared.b16 {%0,%1,%2,%3}, [%4];"
                 : "=r"(r[0]), "=r"(r[1]), "=r"(r[2]), "=r"(r[3]) : "r"(addr));
}
__device__ __forceinline__ unsigned s2u(const void* p) {
    return (unsigned)__cvta_generic_to_shared(p);
}
__device__ __forceinline__ void cpa16(unsigned dst, const void* src, int szvalid) {
    asm volatile("cp.async.cg.shared.global [%0], [%1], 16, %2;"
                 :: "r"(dst), "l"(src), "r"(szvalid) : "memory");
}
#define CP_COMMIT() asm volatile("cp.async.commit_group;" ::: "memory")
#define CP_WAIT1()  asm volatile("cp.async.wait_group 1;" ::: "memory")

// ============================================================
// Kernel 0: zero output + counters + convert X -> fp16 (merged)
// ============================================================
__global__ void zero_cvtX_kernel(float* __restrict__ out, const float* __restrict__ X) {
    int l = blockIdx.x * blockDim.x + threadIdx.x;           // [0, T*H/8)
    if (l < E) g_cnt[l] = 0;
    if (l >= T * H / 8) return;
    size_t off = (size_t)l << 3;
    const float* s = X + off;
    *(uint4*)(g_xh + off) = cvh8(*(const float4*)s, *(const float4*)(s + 4));
    float4 z = make_float4(0.f, 0.f, 0.f, 0.f);
    *(float4*)(out + off)     = z;
    *(float4*)(out + off + 4) = z;
}

// ============================================================
// Kernel 1: convert GUW (interleaved rows) + router (first 2048 warps)
//   dst row r (within expert) = 2j+s  <- src row s*FF + j
// ============================================================
__global__ void cvtGUW_router_kernel(const float* __restrict__ GUW,
                                     const float* __restrict__ X,
                                     const float* __restrict__ GW) {
    int l = blockIdx.x * blockDim.x + threadIdx.x;           // [0, E*2FF*H/8)
    int gwarp = l >> 5;
    int lane  = l & 31;

    // ---- router: one warp per token (warps 0..T-1) ----
    if (gwarp < T) {
        const float* x = X + (size_t)gwarp * H;
        float xr[32];
#pragma unroll
        for (int i = 0; i < 32; i++) xr[i] = x[lane + 32 * i];

        float logit[E];
#pragma unroll
        for (int e = 0; e < E; e++) {
            const float* gw = GW + (size_t)e * H;
            float s = 0.0f;
#pragma unroll
            for (int i = 0; i < 32; i++) s += xr[i] * gw[lane + 32 * i];
#pragma unroll
            for (int off = 16; off > 0; off >>= 1) s += __shfl_xor_sync(0xFFFFFFFFu, s, off);
            logit[e] = s;
        }
        if (lane == 0) {
            int e0 = 0;
            float l0 = logit[0];
#pragma unroll
            for (int e = 1; e < E; e++) if (logit[e] > l0) { l0 = logit[e]; e0 = e; }
            int e1 = -1;
            float l1 = -1e30f;
#pragma unroll
            for (int e = 0; e < E; e++) if (e != e0 && logit[e] > l1) { l1 = logit[e]; e1 = e; }

            float p1 = expf(l1 - l0);
            float inv = 1.0f / (1.0f + p1);

            int s0 = atomicAdd(&g_cnt[e0], 1);
            g_tok[e0 * T + s0]  = gwarp;
            g_prow[e0 * T + s0] = 2 * gwarp;
            g_w[e0 * T + s0]    = inv;
            int s1 = atomicAdd(&g_cnt[e1], 1);
            g_tok[e1 * T + s1]  = gwarp;
            g_prow[e1 * T + s1] = 2 * gwarp + 1;
            g_w[e1 * T + s1]    = p1 * inv;
        }
    }

    // ---- GUW convert ----
    if (l >= E * 2 * FF * (H / 8)) return;
    int k8 = l & (H / 8 - 1);          // 0..127
    int r2 = l >> 7;
    int r  = r2 & (2 * FF - 1);        // 0..8191
    int e  = r2 >> 13;
    int srcrow = e * (2 * FF) + ((r & 1) ? FF : 0) + (r >> 1);
    const float* s = GUW + (size_t)srcrow * H + ((size_t)k8 << 3);
    *(uint4*)(g_guwh + ((size_t)l << 3)) = cvh8(*(const float4*)s, *(const float4*)(s + 4));
}

// ============================================================
// Compute macro: 32x64 warp tile via ldmatrix, one BK=64 slab (4 x k16)
// ============================================================
#define COMPUTE_TILE(ABASE, BBASE)                                            \
    _Pragma("unroll")                                                         \
    for (int ks = 0; ks < 4; ks++) {                                          \
        unsigned a0[4], a1[4], bb[4][4];                                      \
        ldsm4(a0,    (ABASE) + aoff0 + ks * 32);                              \
        ldsm4(a1,    (ABASE) + aoff1 + ks * 32);                              \
        ldsm4(bb[0], (BBASE) + boff0 + ks * 32);                              \
        ldsm4(bb[1], (BBASE) + boff1 + ks * 32);                              \
        ldsm4(bb[2], (BBASE) + boff2 + ks * 32);                              \
        ldsm4(bb[3], (BBASE) + boff3 + ks * 32);                              \
        _Pragma("unroll")                                                     \
        for (int ni = 0; ni < 8; ni++) {                                      \
            mma16(acc[0][ni], a0, &bb[ni >> 1][(ni & 1) * 2]);                \
            mma16(acc[1][ni], a1, &bb[ni >> 1][(ni & 1) * 2]);                \
        }                                                                     \
    }

#define FRAG_OFFSETS()                                                        \
    unsigned aoff0, aoff1, boff0, boff1, boff2, boff3;                        \
    {                                                                         \
        int l15 = lane & 15, lhi = (lane >> 4) << 3;                          \
        aoff0 = (unsigned)(((wm + l15) * AK + lhi) * 2);                      \
        aoff1 = (unsigned)(((wm + 16 + l15) * AK + lhi) * 2);                 \
        int l7 = lane & 7;                                                    \
        int radd = (lane & 16) ? 8 : 0;                                       \
        int kadd = (lane & 8) ? 8 : 0;                                        \
        boff0 = (unsigned)(((wn +  0 + l7 + radd) * AK + kadd) * 2);          \
        boff1 = (unsigned)(((wn + 16 + l7 + radd) * AK + kadd) * 2);          \
        boff2 = (unsigned)(((wn + 32 + l7 + radd) * AK + kadd) * 2);          \
        boff3 = (unsigned)(((wn + 48 + l7 + radd) * AK + kadd) * 2);          \
    }

// ============================================================
// Kernel 2: grouped GEMM1 + GELU fusion (fp16 MMA, 3-stage BK=64)
//   + distributed DW fp32->fp16 convert
// ============================================================
__global__ __launch_bounds__(256, 2) void gemm1_kernel(const float* __restrict__ DW)
{
    int tid = threadIdx.x;

    // ---- distributed DW convert: disjoint slices cover E*H*FF exactly ----
    {
        unsigned b = blockIdx.x + 16u * (blockIdx.y + 64u * blockIdx.z);  // 0..8191
        size_t off = ((size_t)b << 12) + ((size_t)tid << 3);              // b*4096 + tid*8
#pragma unroll
        for (int i = 0; i < 2; i++) {
            const float* s = DW + off + i * 2048;
            *(uint4*)(g_dwh + off + i * 2048) = cvh8(*(const float4*)s, *(const float4*)(s + 4));
        }
    }

    int e   = blockIdx.z;
    int cnt = g_cnt[e];
    int m0  = blockIdx.x * BM;
    if (m0 >= cnt) return;
    int n0c = blockIdx.y * (BN / 2);          // 64 FF columns per CTA

    extern __shared__ char dsm[];
    unsigned sbase = s2u(dsm);

    __shared__ int s_tok[BM];
    __shared__ int s_prow[BM];

    if (tid < BM) {
        int slot = m0 + tid;
        int v = (slot < cnt);
        s_tok[tid]  = v ? g_tok[e * T + slot]  : -1;
        s_prow[tid] = v ? g_prow[e * T + slot] : 0;
    }
    __syncthreads();

    const size_t gu_base = (size_t)e * (2 * FF) + 2 * n0c;   // row base in g_guwh
    int lane = tid & 31, wid = tid >> 5;
    int wm = (wid & 3) * 32, wn = (wid >> 2) * 64;
    int g = lane >> 2, t4 = lane & 3;
    FRAG_OFFSETS();

    int lrow = tid >> 3, lc = tid & 7;        // loader: 8 chunks/row, 32 rows/pass

    float acc[2][8][4];
#pragma unroll
    for (int i = 0; i < 2; i++)
#pragma unroll
        for (int j = 0; j < 8; j++)
#pragma unroll
            for (int k = 0; k < 4; k++) acc[i][j][k] = 0.0f;

#define LOAD_TILE1(S, KT) {                                                   \
    int kof = (KT) * BK;                                                      \
    unsigned ab = sbase + (S) * STG, bb = ab + STG_A;                         \
    _Pragma("unroll")                                                         \
    for (int i = 0; i < 4; i++) {                                             \
        int row = lrow + i * 32;                                              \
        int tk = s_tok[row];                                                  \
        const __half* sa = g_xh + (size_t)(tk < 0 ? 0 : tk) * H + kof + lc * 8; \
        cpa16(ab + row * (AK * 2) + lc * 16, sa, tk >= 0 ? 16 : 0);           \
    }                                                                         \
    _Pragma("unroll")                                                         \
    for (int i = 0; i < 4; i++) {                                             \
        int row = lrow + i * 32;                                              \
        const __half* sb = g_guwh + (gu_base + row) * H + kof + lc * 8;       \
        cpa16(bb + row * (AK * 2) + lc * 16, sb, 16);                         \
    }                                                                         \
}

    LOAD_TILE1(0, 0); CP_COMMIT();
    LOAD_TILE1(1, 1); CP_COMMIT();

    const int nK = H / BK;   // 16
    int st = 0;
    for (int kt = 0; kt < nK; kt++) {
        CP_WAIT1();
        __syncthreads();
        if (kt + 2 < nK) {
            int nst = st + 2; if (nst >= 3) nst -= 3;
            LOAD_TILE1(nst, kt + 2);
        }
        CP_COMMIT();
        unsigned ab = sbase + st * STG;
        COMPUTE_TILE(ab, ab + STG_A);
        st = (st == 2) ? 0 : st + 1;
    }

    // epilogue: hact[prow, n0c + j] = fp16(up * gelu(gate))
#pragma unroll
    for (int mi = 0; mi < 2; mi++) {
        int row0 = wm + mi * 16 + g;
#pragma unroll
        for (int ni = 0; ni < 8; ni++) {
            int j = (wn >> 1) + ni * 4 + t4;
            if (m0 + row0 < cnt) {
                g_hact[(size_t)s_prow[row0] * FF + n0c + j] =
                    __float2half_rn(acc[mi][ni][1] * gelu_exact(acc[mi][ni][0]));
            }
            if (m0 + row0 + 8 < cnt) {
                g_hact[(size_t)s_prow[row0 + 8] * FF + n0c + j] =
                    __float2half_rn(acc[mi][ni][3] * gelu_exact(acc[mi][ni][2]));
            }
        }
    }
#undef LOAD_TILE1
}

// ============================================================
// Kernel 3: grouped GEMM2 + weighted scatter (fp16 MMA, 3-stage BK=64)
// ============================================================
__global__ __launch_bounds__(256, 2) void gemm2_kernel(float* __restrict__ out)
{
    int e   = blockIdx.z;
    int cnt = g_cnt[e];
    int m0  = blockIdx.x * BM;
    if (m0 >= cnt) return;
    int n0  = blockIdx.y * BN;

    extern __shared__ char dsm[];
    unsigned sbase = s2u(dsm);

    __shared__ int   s_prow[BM];
    __shared__ int   s_tok[BM];
    __shared__ float s_w[BM];

    int tid = threadIdx.x;
    if (tid < BM) {
        int slot = m0 + tid;
        int v = (slot < cnt);
        s_prow[tid] = v ? g_prow[e * T + slot] : -1;
        s_tok[tid]  = v ? g_tok[e * T + slot]  : 0;
        s_w[tid]    = v ? g_w[e * T + slot]    : 0.0f;
    }
    __syncthreads();

    const size_t dw_base = (size_t)e * H + n0;   // row base in g_dwh
    int lane = tid & 31, wid = tid >> 5;
    int wm = (wid & 3) * 32, wn = (wid >> 2) * 64;
    int g = lane >> 2, t4 = lane & 3;
    FRAG_OFFSETS();

    int lrow = tid >> 3, lc = tid & 7;

    float acc[2][8][4];
#pragma unroll
    for (int i = 0; i < 2; i++)
#pragma unroll
        for (int j = 0; j < 8; j++)
#pragma unroll
            for (int k = 0; k < 4; k++) acc[i][j][k] = 0.0f;

#define LOAD_TILE2(S, KT) {                                                   \
    int kof = (KT) * BK;                                                      \
    unsigned ab = sbase + (S) * STG, bb = ab + STG_A;                         \
    _Pragma("unroll")                                                         \
    for (int i = 0; i < 4; i++) {                                             \
        int row = lrow + i * 32;                                              \
        int p = s_prow[row];                                                  \
        const __half* sa = g_hact + (size_t)(p < 0 ? 0 : p) * FF + kof + lc * 8; \
        cpa16(ab + row * (AK * 2) + lc * 16, sa, p >= 0 ? 16 : 0);            \
    }                                                                         \
    _Pragma("unroll")                                                         \
    for (int i = 0; i < 4; i++) {                                             \
        int row = lrow + i * 32;                                              \
        const __half* sb = g_dwh + (dw_base + row) * FF + kof + lc * 8;       \
        cpa16(bb + row * (AK * 2) + lc * 16, sb, 16);                         \
    }                                                                         \
}

    LOAD_TILE2(0, 0); CP_COMMIT();
    LOAD_TILE2(1, 1); CP_COMMIT();

    const int nK = FF / BK;   // 64
    int st = 0;
    for (int kt = 0; kt < nK; kt++) {
        CP_WAIT1();
        __syncthreads();
        if (kt + 2 < nK) {
            int nst = st + 2; if (nst >= 3) nst -= 3;
            LOAD_TILE2(nst, kt + 2);
        }
        CP_COMMIT();
        unsigned ab = sbase + st * STG;
        COMPUTE_TILE(ab, ab + STG_A);
        st = (st == 2) ? 0 : st + 1;
    }

    // epilogue: out[t, n] += w * acc (exactly 2 commutative adds per element)
#pragma unroll
    for (int mi = 0; mi < 2; mi++) {
        int row0 = wm + mi * 16 + g;
#pragma unroll
        for (int ni = 0; ni < 8; ni++) {
            int c = wn + ni * 8 + 2 * t4;
            if (m0 + row0 < cnt) {
                int   t  = s_tok[row0];
                float wt = s_w[row0];
                atomicAdd(&out[(size_t)t * H + n0 + c],     wt * acc[mi][ni][0]);
                atomicAdd(&out[(size_t)t * H + n0 + c + 1], wt * acc[mi][ni][1]);
            }
            if (m0 + row0 + 8 < cnt) {
                int   t  = s_tok[row0 + 8];
                float wt = s_w[row0 + 8];
                atomicAdd(&out[(size_t)t * H + n0 + c],     wt * acc[mi][ni][2]);
                atomicAdd(&out[(size_t)t * H + n0 + c + 1], wt * acc[mi][ni][3]);
            }
        }
    }
#undef LOAD_TILE2
}

// ============================================================
extern "C" void kernel_launch(void* const* d_in, const int* in_sizes, int n_in,
                              void* d_out, int out_size) {
    (void)in_sizes; (void)n_in; (void)out_size;
    const float* X   = (const float*)d_in[0];   // hidden_states (1,2048,1024)
    const float* GW  = (const float*)d_in[1];   // gate_w (8,1024)
    const float* GUW = (const float*)d_in[2];   // gate_up_w (8,8192,1024)
    const float* DW  = (const float*)d_in[3];   // down_w (8,1024,4096)
    float* out = (float*)d_out;                 // (1,2048,1024) fp32

    cudaFuncSetAttribute(gemm1_kernel, cudaFuncAttributeMaxDynamicSharedMemorySize, SMEM_BYTES);
    cudaFuncSetAttribute(gemm2_kernel, cudaFuncAttributeMaxDynamicSharedMemorySize, SMEM_BYTES);

    zero_cvtX_kernel<<<(T * H / 8 + 255) / 256, 256>>>(out, X);
    cvtGUW_router_kernel<<<(E * 2 * FF * (H / 8) + 255) / 256, 256>>>(GUW, X, GW);
    // x = M-blocks (fastest-varying) so concurrent CTAs share B tiles in L2
    gemm1_kernel<<<dim3(T / BM, FF / (BN / 2), E), 256, SMEM_BYTES>>>(DW);
    gemm2_kernel<<<dim3(T / BM, H / BN, E), 256, SMEM_BYTES>>>(out);
}

// round 17
// speedup vs baseline: 3.1435x; 1.0237x over previous
#include <cuda_runtime.h>
#include <cuda_fp16.h>
#include <math.h>

// Problem constants
#define H   1024
#define FF  4096
#define E   8
#define T   2048

// GEMM tiling: CTA 128x128x(64 halfs), 4 warps of 64x64, 3-stage cp.async
#define BM  128
#define BN  128
#define BK  64          // halfs per k-tile
#define AK  72          // padded smem row stride (halfs): ldmatrix conflict-free (144B)
#define STG_A (BM * AK * 2)             // 18432 B
#define STG   (STG_A + BN * AK * 2)     // 36864 B per stage
#define SMEM_BYTES (3 * STG)            // 110592 B

// -------- device scratch (no allocations allowed) --------
__device__ int    g_cnt[E];
__device__ int    g_tok[E * T];
__device__ int    g_prow[E * T];
__device__ float  g_w[E * T];
__device__ __half g_hact[(size_t)2 * T * FF];        // 32 MB
__device__ __half g_xh[(size_t)T * H];               // 4 MB  fp16 X
__device__ __half g_guwh[(size_t)E * 2 * FF * H];    // 128 MB fp16 gate_up (interleaved rows)
__device__ __half g_dwh[(size_t)E * H * FF];         // 64 MB fp16 down_w

// -------- helpers --------
__device__ __forceinline__ unsigned pk(float a, float b) {
    __half2 h = __floats2half2_rn(a, b);
    return *(unsigned*)&h;
}
__device__ __forceinline__ uint4 cvh8(float4 a, float4 b) {
    return make_uint4(pk(a.x, a.y), pk(a.z, a.w), pk(b.x, b.y), pk(b.z, b.w));
}
__device__ __forceinline__ float gelu_exact(float x) {
    return 0.5f * x * (1.0f + erff(x * 0.70710678118654752440f));
}
__device__ __forceinline__ void mma16(float* c, const unsigned* a, const unsigned* b) {
    asm("mma.sync.aligned.m16n8k16.row.col.f32.f16.f16.f32 "
        "{%0,%1,%2,%3}, {%4,%5,%6,%7}, {%8,%9}, {%0,%1,%2,%3};\n"
        : "+f"(c[0]), "+f"(c[1]), "+f"(c[2]), "+f"(c[3])
        : "r"(a[0]), "r"(a[1]), "r"(a[2]), "r"(a[3]), "r"(b[0]), "r"(b[1]));
}
__device__ __forceinline__ void ldsm4(unsigned* r, unsigned addr) {
    asm volatile("ldmatrix.sync.aligned.m8n8.x4.shared.b16 {%0,%1,%2,%3}, [%4];"
                 : "=r"(r[0]), "=r"(r[1]), "=r"(r[2]), "=r"(r[3]) : "r"(addr));
}
__device__ __forceinline__ unsigned s2u(const void* p) {
    return (unsigned)__cvta_generic_to_shared(p);
}
__device__ __forceinline__ void cpa16(unsigned dst, const void* src, int szvalid) {
    asm volatile("cp.async.cg.shared.global [%0], [%1], 16, %2;"
                 :: "r"(dst), "l"(src), "r"(szvalid) : "memory");
}
#define CP_COMMIT() asm volatile("cp.async.commit_group;" ::: "memory")
#define CP_WAIT1()  asm volatile("cp.async.wait_group 1;" ::: "memory")

// ============================================================
// Kernel 0: zero output + counters + convert X -> fp16 (merged)
// ============================================================
__global__ void zero_cvtX_kernel(float* __restrict__ out, const float* __restrict__ X) {
    int l = blockIdx.x * blockDim.x + threadIdx.x;           // [0, T*H/8)
    if (l < E) g_cnt[l] = 0;
    if (l >= T * H / 8) return;
    size_t off = (size_t)l << 3;
    const float* s = X + off;
    *(uint4*)(g_xh + off) = cvh8(*(const float4*)s, *(const float4*)(s + 4));
    float4 z = make_float4(0.f, 0.f, 0.f, 0.f);
    *(float4*)(out + off)     = z;
    *(float4*)(out + off + 4) = z;
}

// ============================================================
// Kernel 1: convert GUW (interleaved rows) + router (first 2048 warps)
// ============================================================
__global__ void cvtGUW_router_kernel(const float* __restrict__ GUW,
                                     const float* __restrict__ X,
                                     const float* __restrict__ GW) {
    int l = blockIdx.x * blockDim.x + threadIdx.x;           // [0, E*2FF*H/8)
    int gwarp = l >> 5;
    int lane  = l & 31;

    // ---- router: one warp per token (warps 0..T-1) ----
    if (gwarp < T) {
        const float* x = X + (size_t)gwarp * H;
        float xr[32];
#pragma unroll
        for (int i = 0; i < 32; i++) xr[i] = x[lane + 32 * i];

        float logit[E];
#pragma unroll
        for (int e = 0; e < E; e++) {
            const float* gw = GW + (size_t)e * H;
            float s = 0.0f;
#pragma unroll
            for (int i = 0; i < 32; i++) s += xr[i] * gw[lane + 32 * i];
#pragma unroll
            for (int off = 16; off > 0; off >>= 1) s += __shfl_xor_sync(0xFFFFFFFFu, s, off);
            logit[e] = s;
        }
        if (lane == 0) {
            int e0 = 0;
            float l0 = logit[0];
#pragma unroll
            for (int e = 1; e < E; e++) if (logit[e] > l0) { l0 = logit[e]; e0 = e; }
            int e1 = -1;
            float l1 = -1e30f;
#pragma unroll
            for (int e = 0; e < E; e++) if (e != e0 && logit[e] > l1) { l1 = logit[e]; e1 = e; }

            float p1 = expf(l1 - l0);
            float inv = 1.0f / (1.0f + p1);

            int s0 = atomicAdd(&g_cnt[e0], 1);
            g_tok[e0 * T + s0]  = gwarp;
            g_prow[e0 * T + s0] = 2 * gwarp;
            g_w[e0 * T + s0]    = inv;
            int s1 = atomicAdd(&g_cnt[e1], 1);
            g_tok[e1 * T + s1]  = gwarp;
            g_prow[e1 * T + s1] = 2 * gwarp + 1;
            g_w[e1 * T + s1]    = p1 * inv;
        }
    }

    // ---- GUW convert ----
    if (l >= E * 2 * FF * (H / 8)) return;
    int k8 = l & (H / 8 - 1);          // 0..127
    int r2 = l >> 7;
    int r  = r2 & (2 * FF - 1);        // 0..8191
    int e  = r2 >> 13;
    int srcrow = e * (2 * FF) + ((r & 1) ? FF : 0) + (r >> 1);
    const float* s = GUW + (size_t)srcrow * H + ((size_t)k8 << 3);
    *(uint4*)(g_guwh + ((size_t)l << 3)) = cvh8(*(const float4*)s, *(const float4*)(s + 4));
}

// ============================================================
// Compute macro: 64x64 warp tile via ldmatrix, one BK=64 slab (4 x k16)
//   per ks: 8 LDSM.x4 + 32 HMMA  (A/B redundancy 2x each)
// ============================================================
#define COMPUTE_TILE(ABASE, BBASE)                                            \
    _Pragma("unroll")                                                         \
    for (int ks = 0; ks < 4; ks++) {                                          \
        unsigned a[4][4], b[4][4];                                            \
        ldsm4(a[0], (ABASE) + aoff0 + ks * 32);                               \
        ldsm4(a[1], (ABASE) + aoff1 + ks * 32);                               \
        ldsm4(a[2], (ABASE) + aoff2 + ks * 32);                               \
        ldsm4(a[3], (ABASE) + aoff3 + ks * 32);                               \
        ldsm4(b[0], (BBASE) + boff0 + ks * 32);                               \
        ldsm4(b[1], (BBASE) + boff1 + ks * 32);                               \
        ldsm4(b[2], (BBASE) + boff2 + ks * 32);                               \
        ldsm4(b[3], (BBASE) + boff3 + ks * 32);                               \
        _Pragma("unroll")                                                     \
        for (int mi = 0; mi < 4; mi++)                                        \
            _Pragma("unroll")                                                 \
            for (int ni = 0; ni < 8; ni++)                                    \
                mma16(acc[mi][ni], a[mi], &b[ni >> 1][(ni & 1) * 2]);         \
    }

#define FRAG_OFFSETS()                                                        \
    unsigned aoff0, aoff1, aoff2, aoff3, boff0, boff1, boff2, boff3;          \
    {                                                                         \
        int l15 = lane & 15, lhi = (lane >> 4) << 3;                          \
        aoff0 = (unsigned)(((wm +  0 + l15) * AK + lhi) * 2);                 \
        aoff1 = (unsigned)(((wm + 16 + l15) * AK + lhi) * 2);                 \
        aoff2 = (unsigned)(((wm + 32 + l15) * AK + lhi) * 2);                 \
        aoff3 = (unsigned)(((wm + 48 + l15) * AK + lhi) * 2);                 \
        int l7 = lane & 7;                                                    \
        int radd = (lane & 16) ? 8 : 0;                                       \
        int kadd = (lane & 8) ? 8 : 0;                                        \
        boff0 = (unsigned)(((wn +  0 + l7 + radd) * AK + kadd) * 2);          \
        boff1 = (unsigned)(((wn + 16 + l7 + radd) * AK + kadd) * 2);          \
        boff2 = (unsigned)(((wn + 32 + l7 + radd) * AK + kadd) * 2);          \
        boff3 = (unsigned)(((wn + 48 + l7 + radd) * AK + kadd) * 2);          \
    }

// ============================================================
// Kernel 2: grouped GEMM1 + GELU fusion (fp16 MMA, 3-stage BK=64, 128 thr)
//   + distributed DW fp32->fp16 convert
// ============================================================
__global__ __launch_bounds__(128, 2) void gemm1_kernel(const float* __restrict__ DW)
{
    int tid = threadIdx.x;

    // ---- distributed DW convert: disjoint slices cover E*H*FF exactly ----
    {
        unsigned b = blockIdx.x + 16u * (blockIdx.y + 64u * blockIdx.z);  // 0..8191
        size_t off = ((size_t)b << 12) + ((size_t)tid << 3);              // b*4096 + tid*8
#pragma unroll
        for (int i = 0; i < 4; i++) {
            const float* s = DW + off + i * 1024;
            *(uint4*)(g_dwh + off + i * 1024) = cvh8(*(const float4*)s, *(const float4*)(s + 4));
        }
    }

    int e   = blockIdx.z;
    int cnt = g_cnt[e];
    int m0  = blockIdx.x * BM;
    if (m0 >= cnt) return;
    int n0c = blockIdx.y * (BN / 2);          // 64 FF columns per CTA

    extern __shared__ char dsm[];
    unsigned sbase = s2u(dsm);

    __shared__ int s_tok[BM];
    __shared__ int s_prow[BM];

    if (tid < BM) {
        int slot = m0 + tid;
        int v = (slot < cnt);
        s_tok[tid]  = v ? g_tok[e * T + slot]  : -1;
        s_prow[tid] = v ? g_prow[e * T + slot] : 0;
    }
    __syncthreads();

    const size_t gu_base = (size_t)e * (2 * FF) + 2 * n0c;   // row base in g_guwh
    int lane = tid & 31, wid = tid >> 5;
    int wm = (wid & 1) * 64, wn = (wid >> 1) * 64;
    int g = lane >> 2, t4 = lane & 3;
    FRAG_OFFSETS();

    int lrow = tid >> 3, lc = tid & 7;        // loader: 8 chunks/row, 16 rows/pass

    float acc[4][8][4];
#pragma unroll
    for (int i = 0; i < 4; i++)
#pragma unroll
        for (int j = 0; j < 8; j++)
#pragma unroll
            for (int k = 0; k < 4; k++) acc[i][j][k] = 0.0f;

#define LOAD_TILE1(S, KT) {                                                   \
    int kof = (KT) * BK;                                                      \
    unsigned ab = sbase + (S) * STG, bb = ab + STG_A;                         \
    _Pragma("unroll")                                                         \
    for (int i = 0; i < 8; i++) {                                             \
        int row = lrow + i * 16;                                              \
        int tk = s_tok[row];                                                  \
        const __half* sa = g_xh + (size_t)(tk < 0 ? 0 : tk) * H + kof + lc * 8; \
        cpa16(ab + row * (AK * 2) + lc * 16, sa, tk >= 0 ? 16 : 0);           \
    }                                                                         \
    _Pragma("unroll")                                                         \
    for (int i = 0; i < 8; i++) {                                             \
        int row = lrow + i * 16;                                              \
        const __half* sb = g_guwh + (gu_base + row) * H + kof + lc * 8;       \
        cpa16(bb + row * (AK * 2) + lc * 16, sb, 16);                         \
    }                                                                         \
}

    LOAD_TILE1(0, 0); CP_COMMIT();
    LOAD_TILE1(1, 1); CP_COMMIT();

    const int nK = H / BK;   // 16
    int st = 0;
    for (int kt = 0; kt < nK; kt++) {
        CP_WAIT1();
        __syncthreads();
        if (kt + 2 < nK) {
            int nst = st + 2; if (nst >= 3) nst -= 3;
            LOAD_TILE1(nst, kt + 2);
        }
        CP_COMMIT();
        unsigned ab = sbase + st * STG;
        COMPUTE_TILE(ab, ab + STG_A);
        st = (st == 2) ? 0 : st + 1;
    }

    // epilogue: hact[prow, n0c + j] = fp16(up * gelu(gate))
#pragma unroll
    for (int mi = 0; mi < 4; mi++) {
        int row0 = wm + mi * 16 + g;
#pragma unroll
        for (int ni = 0; ni < 8; ni++) {
            int j = (wn >> 1) + ni * 4 + t4;
            if (m0 + row0 < cnt) {
                g_hact[(size_t)s_prow[row0] * FF + n0c + j] =
                    __float2half_rn(acc[mi][ni][1] * gelu_exact(acc[mi][ni][0]));
            }
            if (m0 + row0 + 8 < cnt) {
                g_hact[(size_t)s_prow[row0 + 8] * FF + n0c + j] =
                    __float2half_rn(acc[mi][ni][3] * gelu_exact(acc[mi][ni][2]));
            }
        }
    }
#undef LOAD_TILE1
}

// ============================================================
// Kernel 3: grouped GEMM2 + weighted scatter (fp16 MMA, 3-stage BK=64, 128 thr)
// ============================================================
__global__ __launch_bounds__(128, 2) void gemm2_kernel(float* __restrict__ out)
{
    int e   = blockIdx.z;
    int cnt = g_cnt[e];
    int m0  = blockIdx.x * BM;
    if (m0 >= cnt) return;
    int n0  = blockIdx.y * BN;

    extern __shared__ char dsm[];
    unsigned sbase = s2u(dsm);

    __shared__ int   s_prow[BM];
    __shared__ int   s_tok[BM];
    __shared__ float s_w[BM];

    int tid = threadIdx.x;
    if (tid < BM) {
        int slot = m0 + tid;
        int v = (slot < cnt);
        s_prow[tid] = v ? g_prow[e * T + slot] : -1;
        s_tok[tid]  = v ? g_tok[e * T + slot]  : 0;
        s_w[tid]    = v ? g_w[e * T + slot]    : 0.0f;
    }
    __syncthreads();

    const size_t dw_base = (size_t)e * H + n0;   // row base in g_dwh
    int lane = tid & 31, wid = tid >> 5;
    int wm = (wid & 1) * 64, wn = (wid >> 1) * 64;
    int g = lane >> 2, t4 = lane & 3;
    FRAG_OFFSETS();

    int lrow = tid >> 3, lc = tid & 7;

    float acc[4][8][4];
#pragma unroll
    for (int i = 0; i < 4; i++)
#pragma unroll
        for (int j = 0; j < 8; j++)
#pragma unroll
            for (int k = 0; k < 4; k++) acc[i][j][k] = 0.0f;

#define LOAD_TILE2(S, KT) {                                                   \
    int kof = (KT) * BK;                                                      \
    unsigned ab = sbase + (S) * STG, bb = ab + STG_A;                         \
    _Pragma("unroll")                                                         \
    for (int i = 0; i < 8; i++) {                                             \
        int row = lrow + i * 16;                                              \
        int p = s_prow[row];                                                  \
        const __half* sa = g_hact + (size_t)(p < 0 ? 0 : p) * FF + kof + lc * 8; \
        cpa16(ab + row * (AK * 2) + lc * 16, sa, p >= 0 ? 16 : 0);            \
    }                                                                         \
    _Pragma("unroll")                                                         \
    for (int i = 0; i < 8; i++) {                                             \
        int row = lrow + i * 16;                                              \
        const __half* sb = g_dwh + (dw_base + row) * FF + kof + lc * 8;       \
        cpa16(bb + row * (AK * 2) + lc * 16, sb, 16);                         \
    }                                                                         \
}

    LOAD_TILE2(0, 0); CP_COMMIT();
    LOAD_TILE2(1, 1); CP_COMMIT();

    const int nK = FF / BK;   // 64
    int st = 0;
    for (int kt = 0; kt < nK; kt++) {
        CP_WAIT1();
        __syncthreads();
        if (kt + 2 < nK) {
            int nst = st + 2; if (nst >= 3) nst -= 3;
            LOAD_TILE2(nst, kt + 2);
        }
        CP_COMMIT();
        unsigned ab = sbase + st * STG;
        COMPUTE_TILE(ab, ab + STG_A);
        st = (st == 2) ? 0 : st + 1;
    }

    // epilogue: out[t, n] += w * acc (exactly 2 commutative adds per element)
#pragma unroll
    for (int mi = 0; mi < 4; mi++) {
        int row0 = wm + mi * 16 + g;
#pragma unroll
        for (int ni = 0; ni < 8; ni++) {
            int c = wn + ni * 8 + 2 * t4;
            if (m0 + row0 < cnt) {
                int   t  = s_tok[row0];
                float wt = s_w[row0];
                atomicAdd(&out[(size_t)t * H + n0 + c],     wt * acc[mi][ni][0]);
                atomicAdd(&out[(size_t)t * H + n0 + c + 1], wt * acc[mi][ni][1]);
            }
            if (m0 + row0 + 8 < cnt) {
                int   t  = s_tok[row0 + 8];
                float wt = s_w[row0 + 8];
                atomicAdd(&out[(size_t)t * H + n0 + c],     wt * acc[mi][ni][2]);
                atomicAdd(&out[(size_t)t * H + n0 + c + 1], wt * acc[mi][ni][3]);
            }
        }
    }
#undef LOAD_TILE2
}

// ============================================================
extern "C" void kernel_launch(void* const* d_in, const int* in_sizes, int n_in,
                              void* d_out, int out_size) {
    (void)in_sizes; (void)n_in; (void)out_size;
    const float* X   = (const float*)d_in[0];   // hidden_states (1,2048,1024)
    const float* GW  = (const float*)d_in[1];   // gate_w (8,1024)
    const float* GUW = (const float*)d_in[2];   // gate_up_w (8,8192,1024)
    const float* DW  = (const float*)d_in[3];   // down_w (8,1024,4096)
    float* out = (float*)d_out;                 // (1,2048,1024) fp32

    cudaFuncSetAttribute(gemm1_kernel, cudaFuncAttributeMaxDynamicSharedMemorySize, SMEM_BYTES);
    cudaFuncSetAttribute(gemm2_kernel, cudaFuncAttributeMaxDynamicSharedMemorySize, SMEM_BYTES);

    zero_cvtX_kernel<<<(T * H / 8 + 255) / 256, 256>>>(out, X);
    cvtGUW_router_kernel<<<(E * 2 * FF * (H / 8) + 255) / 256, 256>>>(GUW, X, GW);
    // x = M-blocks (fastest-varying) so concurrent CTAs share B tiles in L2
    gemm1_kernel<<<dim3(T / BM, FF / (BN / 2), E), 128, SMEM_BYTES>>>(DW);
    gemm2_kernel<<<dim3(T / BM, H / BN, E), 128, SMEM_BYTES>>>(out);
}